// round 1
// baseline (speedup 1.0000x reference)
#include <cuda_runtime.h>
#include <cuda_fp16.h>

// ---------------------------------------------------------------------------
// GFocalV2 head, fused: two 3-layer MLPs on 294912x256 activations via
// mma.sync fp16 (fp32 accum), plus softmax/top-k/quality epilogue in-kernel.
// ---------------------------------------------------------------------------

namespace cfg {
constexpr int C    = 256;
constexpr int NB   = 17;          // reg_max + 1
constexpr int R4   = 68;          // 4 * NB
constexpr int NIMG = 32;
constexpr int HH   = 96, WW = 96;
constexpr int L    = HH * WW;
constexpr int P    = NIMG * L;    // 294912 rows
constexpr int TM   = 128;         // rows per CTA
constexpr int NBLK = P / TM;      // 2304 (exact)
constexpr int PITCH = 264;        // halves per smem row (odd word pitch -> no bank conflicts)

// fp16 weight scratch offsets (in halves)
constexpr int WC1 = 0;
constexpr int WC2 = 65536;
constexpr int WR1 = 131072;
constexpr int WR2 = 196608;
constexpr int WR3 = 262144;       // 68*256
constexpr int WTOT = 279552;

// dynamic smem layout (bytes)
constexpr int SA_OFF    = 0;                        // half[128*264]
constexpr int SB_OFF    = TM * PITCH * 2;           // 67584: weight stage
constexpr int SH_OFF    = 2 * TM * PITCH * 2;       // 135168: half buf / fp32 reg_pred
constexpr int SSTAT_OFF = SH_OFF + TM * R4 * 4;     // 169984: fp32 [128][21]
constexpr int SQ_OFF    = 3 * TM * PITCH * 2;       // 202752: quality[128]
constexpr int QW1_OFF   = SQ_OFF + 512;             // 64*20 f32
constexpr int QB1_OFF   = QW1_OFF + 5120;
constexpr int QW2_OFF   = QB1_OFF + 256;
constexpr int CW3_OFF   = QW2_OFF + 256;            // 256 f32
constexpr int SMEM_BYTES = CW3_OFF + 1024;          // 209920 B
}  // namespace cfg

__device__ __align__(16) __half g_wh[cfg::WTOT];

// ------------------------- weight fp32 -> fp16 -----------------------------
__global__ void convert_weights_kernel(const float* __restrict__ cw1,
                                       const float* __restrict__ cw2,
                                       const float* __restrict__ rw1,
                                       const float* __restrict__ rw2,
                                       const float* __restrict__ rw3) {
    int i = blockIdx.x * blockDim.x + threadIdx.x;
    if (i < 65536)            g_wh[i] = __float2half(cw1[i]);
    else if (i < 131072)      g_wh[i] = __float2half(cw2[i - 65536]);
    else if (i < 196608)      g_wh[i] = __float2half(rw1[i - 131072]);
    else if (i < 262144)      g_wh[i] = __float2half(rw2[i - 196608]);
    else if (i < cfg::WTOT)   g_wh[i] = __float2half(rw3[i - 262144]);
}

// ------------------------------- helpers -----------------------------------
__device__ __forceinline__ void mma16816(float d[4],
                                         unsigned a0, unsigned a1, unsigned a2, unsigned a3,
                                         unsigned b0, unsigned b1) {
    asm volatile(
        "mma.sync.aligned.m16n8k16.row.col.f32.f16.f16.f32 "
        "{%0,%1,%2,%3}, {%4,%5,%6,%7}, {%8,%9}, {%0,%1,%2,%3};\n"
        : "+f"(d[0]), "+f"(d[1]), "+f"(d[2]), "+f"(d[3])
        : "r"(a0), "r"(a1), "r"(a2), "r"(a3), "r"(b0), "r"(b1));
}

// stage 128 rows x 256 f32 -> fp16 into pitched smem
__device__ __forceinline__ void stage_x(const float* __restrict__ gX, __half* sA, int tid) {
    const float4* src = (const float4*)gX;
    #pragma unroll 4
    for (int i = tid; i < 128 * 64; i += 256) {
        int r = i >> 6, c = i & 63;
        float4 v = src[r * 64 + c];
        __half2 h0 = __floats2half2_rn(v.x, v.y);
        __half2 h1 = __floats2half2_rn(v.z, v.w);
        uint2 pk;
        pk.x = *reinterpret_cast<unsigned*>(&h0);
        pk.y = *reinterpret_cast<unsigned*>(&h1);
        *reinterpret_cast<uint2*>(sA + r * cfg::PITCH + c * 4) = pk;
    }
}

// stage up to 128 weight rows (x256 halves) from global -> pitched smem, zero pad
__device__ __forceinline__ void stage_w(const __half* __restrict__ gW, int rows,
                                        __half* sW, int tid) {
    const uint4* src = (const uint4*)gW;
    #pragma unroll 4
    for (int i = tid; i < 128 * 32; i += 256) {
        int r = i >> 5, c = i & 31;
        uint4 v = make_uint4(0u, 0u, 0u, 0u);
        if (r < rows) v = src[r * 32 + c];
        *reinterpret_cast<uint4*>(sW + r * cfg::PITCH + c * 8) = v;
    }
}

// 128x128 tile = sIn(128x256 f16) * sW(128x256 f16)^T, fp32 accum.
__device__ __forceinline__ void mma_block(const __half* sIn, const __half* sW,
                                          float acc[2][8][4],
                                          int wm, int wn, int g, int c2) {
    #pragma unroll
    for (int mi = 0; mi < 2; ++mi)
        #pragma unroll
        for (int ni = 0; ni < 8; ++ni)
            #pragma unroll
            for (int j = 0; j < 4; ++j) acc[mi][ni][j] = 0.f;

    const unsigned* A32 = (const unsigned*)sIn;
    const unsigned* B32 = (const unsigned*)sW;
    const int ar = wm * 32 + g;
    const int bc = wn * 64 + g;
    #pragma unroll 4
    for (int k0 = 0; k0 < 16; ++k0) {
        const int kw = k0 * 8 + c2;   // 32-bit word offset in a row
        unsigned a[2][4];
        #pragma unroll
        for (int mi = 0; mi < 2; ++mi) {
            int r0 = ar + mi * 16;
            a[mi][0] = A32[r0 * 132 + kw];
            a[mi][1] = A32[(r0 + 8) * 132 + kw];
            a[mi][2] = A32[r0 * 132 + kw + 4];
            a[mi][3] = A32[(r0 + 8) * 132 + kw + 4];
        }
        #pragma unroll
        for (int ni = 0; ni < 8; ++ni) {
            int br = bc + ni * 8;
            unsigned b0 = B32[br * 132 + kw];
            unsigned b1 = B32[br * 132 + kw + 4];
            mma16816(acc[0][ni], a[0][0], a[0][1], a[0][2], a[0][3], b0, b1);
            mma16816(acc[1][ni], a[1][0], a[1][1], a[1][2], a[1][3], b0, b1);
        }
    }
}

__device__ __forceinline__ void epilogue_hidden(float acc[2][8][4],
                                                const float* __restrict__ bias,
                                                int outBase, __half* sOut,
                                                int wm, int wn, int g, int c2) {
    #pragma unroll
    for (int mi = 0; mi < 2; ++mi) {
        int m = wm * 32 + mi * 16 + g;
        #pragma unroll
        for (int ni = 0; ni < 8; ++ni) {
            int n = outBase + wn * 64 + ni * 8 + c2 * 2;
            float b0 = __ldg(bias + n), b1 = __ldg(bias + n + 1);
            float v0 = fmaxf(acc[mi][ni][0] + b0, 0.f);
            float v1 = fmaxf(acc[mi][ni][1] + b1, 0.f);
            float v2 = fmaxf(acc[mi][ni][2] + b0, 0.f);
            float v3 = fmaxf(acc[mi][ni][3] + b1, 0.f);
            *reinterpret_cast<__half2*>(sOut + m * cfg::PITCH + n)       = __floats2half2_rn(v0, v1);
            *reinterpret_cast<__half2*>(sOut + (m + 8) * cfg::PITCH + n) = __floats2half2_rn(v2, v3);
        }
    }
}

__device__ __forceinline__ void epilogue_reg(float acc[2][8][4],
                                             const float* __restrict__ bias,
                                             float* sReg, float* __restrict__ gReg,
                                             int row0, int wm, int wn, int g, int c2) {
    #pragma unroll
    for (int mi = 0; mi < 2; ++mi) {
        int m = wm * 32 + mi * 16 + g;
        #pragma unroll
        for (int ni = 0; ni < 8; ++ni) {
            int n = wn * 64 + ni * 8 + c2 * 2;
            if (n < cfg::R4) {
                float b0 = __ldg(bias + n), b1 = __ldg(bias + n + 1);
                float2 lo = make_float2(acc[mi][ni][0] + b0, acc[mi][ni][1] + b1);
                float2 hi = make_float2(acc[mi][ni][2] + b0, acc[mi][ni][3] + b1);
                *reinterpret_cast<float2*>(sReg + m * cfg::R4 + n) = lo;
                *reinterpret_cast<float2*>(sReg + (m + 8) * cfg::R4 + n) = hi;
                *reinterpret_cast<float2*>(gReg + (size_t)(row0 + m) * cfg::R4 + n) = lo;
                *reinterpret_cast<float2*>(gReg + (size_t)(row0 + m + 8) * cfg::R4 + n) = hi;
            }
        }
    }
}

// ------------------------------ main kernel --------------------------------
__global__ __launch_bounds__(256, 1)
void gfocal_head_kernel(const float* __restrict__ x,
                        const float* __restrict__ cb1, const float* __restrict__ cb2,
                        const float* __restrict__ cw3, const float* __restrict__ cb3,
                        const float* __restrict__ rb1, const float* __restrict__ rb2,
                        const float* __restrict__ rb3,
                        const float* __restrict__ qw1, const float* __restrict__ qb1,
                        const float* __restrict__ qw2, const float* __restrict__ qb2,
                        float* __restrict__ out) {
    using namespace cfg;
    extern __shared__ char smem[];
    __half* sA    = (__half*)(smem + SA_OFF);
    __half* sB    = (__half*)(smem + SB_OFF);
    __half* sH    = (__half*)(smem + SH_OFF);
    float*  sReg  = (float*)(smem + SH_OFF);      // aliases sH (fp32 reg_pred)
    float*  sStat = (float*)(smem + SSTAT_OFF);   // [128][21]
    float*  sQual = (float*)(smem + SQ_OFF);
    float*  sQw1  = (float*)(smem + QW1_OFF);
    float*  sQb1  = (float*)(smem + QB1_OFF);
    float*  sQw2  = (float*)(smem + QW2_OFF);
    float*  sCw3  = (float*)(smem + CW3_OFF);

    const int tid  = threadIdx.x;
    const int warp = tid >> 5, lane = tid & 31;
    const int wm = warp >> 1, wn = warp & 1;
    const int g = lane >> 2, c2 = lane & 3;
    const int row0 = blockIdx.x * TM;

    float* out_cls = out;
    float* out_box = out + (size_t)P;
    float* out_reg = out + (size_t)P * 5;

    // stage X + small weights
    stage_x(x + (size_t)row0 * C, sA, tid);
    for (int i = tid; i < 1280; i += 256) sQw1[i] = qw1[i];
    if (tid < 64) { sQb1[tid] = qb1[tid]; sQw2[tid] = qw2[tid]; }
    sCw3[tid] = cw3[tid];
    __syncthreads();

    float acc[2][8][4];

    // ---------------- regression branch ----------------
    #pragma unroll 1
    for (int hg = 0; hg < 2; ++hg) {          // h1r = relu(X @ rw1^T + rb1) -> sH
        stage_w(g_wh + WR1 + hg * 32768, 128, sB, tid);
        __syncthreads();
        mma_block(sA, sB, acc, wm, wn, g, c2);
        epilogue_hidden(acc, rb1, hg * 128, sH, wm, wn, g, c2);
        __syncthreads();
    }
    #pragma unroll 1
    for (int hg = 0; hg < 2; ++hg) {          // h2r = relu(h1r @ rw2^T + rb2) -> sA
        stage_w(g_wh + WR2 + hg * 32768, 128, sB, tid);
        __syncthreads();
        mma_block(sH, sB, acc, wm, wn, g, c2);
        epilogue_hidden(acc, rb2, hg * 128, sA, wm, wn, g, c2);
        __syncthreads();
    }
    // reg_pred = h2r @ rw3^T + rb3 -> sReg (fp32) + global output
    stage_w(g_wh + WR3, R4, sB, tid);
    __syncthreads();
    mma_block(sA, sB, acc, wm, wn, g, c2);
    epilogue_reg(acc, rb3, sReg, out_reg, row0, wm, wn, g, c2);
    __syncthreads();

    // ---------------- per-position stats: softmax, box, top4 ----------------
    {
        int row = tid >> 1;
        int dbase = (tid & 1) * 2;
        #pragma unroll
        for (int dd = 0; dd < 2; ++dd) {
            int d = dbase + dd;
            const float* rp = sReg + row * R4 + d * NB;
            float pb[NB];
            float mx = -1e30f;
            #pragma unroll
            for (int b = 0; b < NB; ++b) { pb[b] = rp[b]; mx = fmaxf(mx, pb[b]); }
            float s = 0.f, sbi = 0.f;
            #pragma unroll
            for (int b = 0; b < NB; ++b) {
                float e = __expf(pb[b] - mx);
                pb[b] = e; s += e; sbi += e * (float)b;
            }
            float inv = 1.f / s;
            out_box[(size_t)(row0 + row) * 4 + d] = sbi * inv * (1.0f / 16.0f);
            unsigned mask = 0; float tsum = 0.f;
            #pragma unroll
            for (int j = 0; j < 4; ++j) {
                float m = -1e30f; int mi = 0;
                #pragma unroll
                for (int b = 0; b < NB; ++b) {
                    bool ok = !((mask >> b) & 1u) && (pb[b] > m);
                    if (ok) { m = pb[b]; mi = b; }
                }
                mask |= (1u << mi);
                tsum += m;
                sStat[row * 21 + d * 5 + j] = m * inv;
            }
            sStat[row * 21 + d * 5 + 4] = tsum * inv * 0.25f;
        }
    }
    __syncthreads();

    // quality = sigmoid(qw2 @ relu(qw1 @ stat + qb1) + qb2)
    if (tid < TM) {
        const float* st = sStat + tid * 21;
        float q = __ldg(qb2);
        #pragma unroll 4
        for (int o = 0; o < 64; ++o) {
            float h = sQb1[o];
            #pragma unroll
            for (int c = 0; c < 20; ++c) h += sQw1[o * 20 + c] * st[c];
            q += sQw2[o] * fmaxf(h, 0.f);
        }
        sQual[tid] = 1.f / (1.f + __expf(-q));
    }
    // reload X (sA held h2r, done with it)
    stage_x(x + (size_t)row0 * C, sA, tid);
    __syncthreads();

    // ---------------- classification branch ----------------
    #pragma unroll 1
    for (int hg = 0; hg < 2; ++hg) {          // h1c -> sH (sReg/sStat dead now)
        stage_w(g_wh + WC1 + hg * 32768, 128, sB, tid);
        __syncthreads();
        mma_block(sA, sB, acc, wm, wn, g, c2);
        epilogue_hidden(acc, cb1, hg * 128, sH, wm, wn, g, c2);
        __syncthreads();
    }
    #pragma unroll 1
    for (int hg = 0; hg < 2; ++hg) {          // h2c -> sA
        stage_w(g_wh + WC2 + hg * 32768, 128, sB, tid);
        __syncthreads();
        mma_block(sH, sB, acc, wm, wn, g, c2);
        epilogue_hidden(acc, cb2, hg * 128, sA, wm, wn, g, c2);
        __syncthreads();
    }
    // cls score = sigmoid(h2c . cw3 + cb3) * quality
    if (tid < TM) {
        const __half2* hrow = (const __half2*)sA + tid * (PITCH / 2);
        float a = __ldg(cb3);
        #pragma unroll 8
        for (int k = 0; k < 128; ++k) {
            float2 v = __half22float2(hrow[k]);
            a += v.x * sCw3[2 * k] + v.y * sCw3[2 * k + 1];
        }
        float csig = 1.f / (1.f + __expf(-a));
        out_cls[row0 + tid] = csig * sQual[tid];
    }
}

// ------------------------------ launcher -----------------------------------
extern "C" void kernel_launch(void* const* d_in, const int* in_sizes, int n_in,
                              void* d_out, int out_size) {
    const float* x   = (const float*)d_in[0];
    const float* cw1 = (const float*)d_in[1];
    const float* cb1 = (const float*)d_in[2];
    const float* cw2 = (const float*)d_in[3];
    const float* cb2 = (const float*)d_in[4];
    const float* cw3 = (const float*)d_in[5];
    const float* cb3 = (const float*)d_in[6];
    const float* rw1 = (const float*)d_in[7];
    const float* rb1 = (const float*)d_in[8];
    const float* rw2 = (const float*)d_in[9];
    const float* rb2 = (const float*)d_in[10];
    const float* rw3 = (const float*)d_in[11];
    const float* rb3 = (const float*)d_in[12];
    const float* qw1 = (const float*)d_in[13];
    const float* qb1 = (const float*)d_in[14];
    const float* qw2 = (const float*)d_in[15];
    const float* qb2 = (const float*)d_in[16];
    float* out = (float*)d_out;

    cudaFuncSetAttribute(gfocal_head_kernel,
                         cudaFuncAttributeMaxDynamicSharedMemorySize, cfg::SMEM_BYTES);

    convert_weights_kernel<<<(cfg::WTOT + 255) / 256, 256>>>(cw1, cw2, rw1, rw2, rw3);
    gfocal_head_kernel<<<cfg::NBLK, 256, cfg::SMEM_BYTES>>>(
        x, cb1, cb2, cw3, cb3, rb1, rb2, rb3, qw1, qb1, qw2, qb2, out);
}

// round 2
// speedup vs baseline: 1.0068x; 1.0068x over previous
#include <cuda_runtime.h>
#include <cuda_fp16.h>

// ---------------------------------------------------------------------------
// GFocalV2 head, fused: two 3-layer MLPs on 294912x256 activations via
// mma.sync fp16 (fp32 accum), plus softmax/top-k/quality epilogue in-kernel.
// ---------------------------------------------------------------------------

namespace cfg {
constexpr int C    = 256;
constexpr int NB   = 17;          // reg_max + 1
constexpr int R4   = 68;          // 4 * NB
constexpr int NIMG = 32;
constexpr int HH   = 96, WW = 96;
constexpr int L    = HH * WW;
constexpr int P    = NIMG * L;    // 294912 rows
constexpr int TM   = 128;         // rows per CTA
constexpr int NBLK = P / TM;      // 2304 (exact)
constexpr int PITCH = 264;        // halves per smem row (odd word pitch -> no bank conflicts)

// fp16 weight scratch offsets (in halves)
constexpr int WC1 = 0;
constexpr int WC2 = 65536;
constexpr int WR1 = 131072;
constexpr int WR2 = 196608;
constexpr int WR3 = 262144;       // 68*256
constexpr int WTOT = 279552;

// dynamic smem layout (bytes)
constexpr int SA_OFF    = 0;                        // half[128*264]
constexpr int SB_OFF    = TM * PITCH * 2;           // 67584: weight stage
constexpr int SH_OFF    = 2 * TM * PITCH * 2;       // 135168: half buf / fp32 reg_pred
constexpr int SSTAT_OFF = SH_OFF + TM * R4 * 4;     // 169984: fp32 [128][21]
constexpr int SQ_OFF    = 3 * TM * PITCH * 2;       // 202752: quality[128]
constexpr int QW1_OFF   = SQ_OFF + 512;             // 64*20 f32
constexpr int QB1_OFF   = QW1_OFF + 5120;
constexpr int QW2_OFF   = QB1_OFF + 256;
constexpr int CW3_OFF   = QW2_OFF + 256;            // 256 f32
constexpr int SMEM_BYTES = CW3_OFF + 1024;          // 209920 B
}  // namespace cfg

__device__ __align__(16) __half g_wh[cfg::WTOT];

// ------------------------- weight fp32 -> fp16 -----------------------------
__global__ void convert_weights_kernel(const float* __restrict__ cw1,
                                       const float* __restrict__ cw2,
                                       const float* __restrict__ rw1,
                                       const float* __restrict__ rw2,
                                       const float* __restrict__ rw3) {
    int i = blockIdx.x * blockDim.x + threadIdx.x;
    if (i < 65536)            g_wh[i] = __float2half(cw1[i]);
    else if (i < 131072)      g_wh[i] = __float2half(cw2[i - 65536]);
    else if (i < 196608)      g_wh[i] = __float2half(rw1[i - 131072]);
    else if (i < 262144)      g_wh[i] = __float2half(rw2[i - 196608]);
    else if (i < cfg::WTOT)   g_wh[i] = __float2half(rw3[i - 262144]);
}

// ------------------------------- helpers -----------------------------------
__device__ __forceinline__ void mma16816(float d[4],
                                         unsigned a0, unsigned a1, unsigned a2, unsigned a3,
                                         unsigned b0, unsigned b1) {
    asm volatile(
        "mma.sync.aligned.m16n8k16.row.col.f32.f16.f16.f32 "
        "{%0,%1,%2,%3}, {%4,%5,%6,%7}, {%8,%9}, {%0,%1,%2,%3};\n"
        : "+f"(d[0]), "+f"(d[1]), "+f"(d[2]), "+f"(d[3])
        : "r"(a0), "r"(a1), "r"(a2), "r"(a3), "r"(b0), "r"(b1));
}

// stage 128 rows x 256 f32 -> fp16 into pitched smem
__device__ __forceinline__ void stage_x(const float* __restrict__ gX, __half* sA, int tid) {
    const float4* src = (const float4*)gX;
    #pragma unroll 4
    for (int i = tid; i < 128 * 64; i += 256) {
        int r = i >> 6, c = i & 63;
        float4 v = src[r * 64 + c];
        __half2 h0 = __floats2half2_rn(v.x, v.y);
        __half2 h1 = __floats2half2_rn(v.z, v.w);
        uint2 pk;
        pk.x = *reinterpret_cast<unsigned*>(&h0);
        pk.y = *reinterpret_cast<unsigned*>(&h1);
        *reinterpret_cast<uint2*>(sA + r * cfg::PITCH + c * 4) = pk;
    }
}

// stage up to 128 weight rows (x256 halves) from global -> pitched smem, zero pad
__device__ __forceinline__ void stage_w(const __half* __restrict__ gW, int rows,
                                        __half* sW, int tid) {
    const uint4* src = (const uint4*)gW;
    #pragma unroll 4
    for (int i = tid; i < 128 * 32; i += 256) {
        int r = i >> 5, c = i & 31;
        uint4 v = make_uint4(0u, 0u, 0u, 0u);
        if (r < rows) v = src[r * 32 + c];
        *reinterpret_cast<uint4*>(sW + r * cfg::PITCH + c * 8) = v;
    }
}

// 128x128 tile = sIn(128x256 f16) * sW(128x256 f16)^T, fp32 accum.
__device__ __forceinline__ void mma_block(const __half* sIn, const __half* sW,
                                          float acc[2][8][4],
                                          int wm, int wn, int g, int c2) {
    #pragma unroll
    for (int mi = 0; mi < 2; ++mi)
        #pragma unroll
        for (int ni = 0; ni < 8; ++ni)
            #pragma unroll
            for (int j = 0; j < 4; ++j) acc[mi][ni][j] = 0.f;

    const unsigned* A32 = (const unsigned*)sIn;
    const unsigned* B32 = (const unsigned*)sW;
    const int ar = wm * 32 + g;
    const int bc = wn * 64 + g;
    #pragma unroll 4
    for (int k0 = 0; k0 < 16; ++k0) {
        const int kw = k0 * 8 + c2;   // 32-bit word offset in a row
        unsigned a[2][4];
        #pragma unroll
        for (int mi = 0; mi < 2; ++mi) {
            int r0 = ar + mi * 16;
            a[mi][0] = A32[r0 * 132 + kw];
            a[mi][1] = A32[(r0 + 8) * 132 + kw];
            a[mi][2] = A32[r0 * 132 + kw + 4];
            a[mi][3] = A32[(r0 + 8) * 132 + kw + 4];
        }
        #pragma unroll
        for (int ni = 0; ni < 8; ++ni) {
            int br = bc + ni * 8;
            unsigned b0 = B32[br * 132 + kw];
            unsigned b1 = B32[br * 132 + kw + 4];
            mma16816(acc[0][ni], a[0][0], a[0][1], a[0][2], a[0][3], b0, b1);
            mma16816(acc[1][ni], a[1][0], a[1][1], a[1][2], a[1][3], b0, b1);
        }
    }
}

__device__ __forceinline__ void epilogue_hidden(float acc[2][8][4],
                                                const float* __restrict__ bias,
                                                int outBase, __half* sOut,
                                                int wm, int wn, int g, int c2) {
    #pragma unroll
    for (int mi = 0; mi < 2; ++mi) {
        int m = wm * 32 + mi * 16 + g;
        #pragma unroll
        for (int ni = 0; ni < 8; ++ni) {
            int n = outBase + wn * 64 + ni * 8 + c2 * 2;
            float b0 = __ldg(bias + n), b1 = __ldg(bias + n + 1);
            float v0 = fmaxf(acc[mi][ni][0] + b0, 0.f);
            float v1 = fmaxf(acc[mi][ni][1] + b1, 0.f);
            float v2 = fmaxf(acc[mi][ni][2] + b0, 0.f);
            float v3 = fmaxf(acc[mi][ni][3] + b1, 0.f);
            *reinterpret_cast<__half2*>(sOut + m * cfg::PITCH + n)       = __floats2half2_rn(v0, v1);
            *reinterpret_cast<__half2*>(sOut + (m + 8) * cfg::PITCH + n) = __floats2half2_rn(v2, v3);
        }
    }
}

__device__ __forceinline__ void epilogue_reg(float acc[2][8][4],
                                             const float* __restrict__ bias,
                                             float* sReg, float* __restrict__ gReg,
                                             int row0, int wm, int wn, int g, int c2) {
    #pragma unroll
    for (int mi = 0; mi < 2; ++mi) {
        int m = wm * 32 + mi * 16 + g;
        #pragma unroll
        for (int ni = 0; ni < 8; ++ni) {
            int n = wn * 64 + ni * 8 + c2 * 2;
            if (n < cfg::R4) {
                float b0 = __ldg(bias + n), b1 = __ldg(bias + n + 1);
                float2 lo = make_float2(acc[mi][ni][0] + b0, acc[mi][ni][1] + b1);
                float2 hi = make_float2(acc[mi][ni][2] + b0, acc[mi][ni][3] + b1);
                *reinterpret_cast<float2*>(sReg + m * cfg::R4 + n) = lo;
                *reinterpret_cast<float2*>(sReg + (m + 8) * cfg::R4 + n) = hi;
                *reinterpret_cast<float2*>(gReg + (size_t)(row0 + m) * cfg::R4 + n) = lo;
                *reinterpret_cast<float2*>(gReg + (size_t)(row0 + m + 8) * cfg::R4 + n) = hi;
            }
        }
    }
}

// ------------------------------ main kernel --------------------------------
__global__ __launch_bounds__(256, 1)
void gfocal_head_kernel(const float* __restrict__ x,
                        const float* __restrict__ cb1, const float* __restrict__ cb2,
                        const float* __restrict__ cw3, const float* __restrict__ cb3,
                        const float* __restrict__ rb1, const float* __restrict__ rb2,
                        const float* __restrict__ rb3,
                        const float* __restrict__ qw1, const float* __restrict__ qb1,
                        const float* __restrict__ qw2, const float* __restrict__ qb2,
                        float* __restrict__ out) {
    using namespace cfg;
    extern __shared__ char smem[];
    __half* sA    = (__half*)(smem + SA_OFF);
    __half* sB    = (__half*)(smem + SB_OFF);
    __half* sH    = (__half*)(smem + SH_OFF);
    float*  sReg  = (float*)(smem + SH_OFF);      // aliases sH (fp32 reg_pred)
    float*  sStat = (float*)(smem + SSTAT_OFF);   // [128][21]
    float*  sQual = (float*)(smem + SQ_OFF);
    float*  sQw1  = (float*)(smem + QW1_OFF);
    float*  sQb1  = (float*)(smem + QB1_OFF);
    float*  sQw2  = (float*)(smem + QW2_OFF);
    float*  sCw3  = (float*)(smem + CW3_OFF);

    const int tid  = threadIdx.x;
    const int warp = tid >> 5, lane = tid & 31;
    const int wm = warp >> 1, wn = warp & 1;
    const int g = lane >> 2, c2 = lane & 3;
    const int row0 = blockIdx.x * TM;

    float* out_cls = out;
    float* out_box = out + (size_t)P;
    float* out_reg = out + (size_t)P * 5;

    // stage X + small weights
    stage_x(x + (size_t)row0 * C, sA, tid);
    for (int i = tid; i < 1280; i += 256) sQw1[i] = qw1[i];
    if (tid < 64) { sQb1[tid] = qb1[tid]; sQw2[tid] = qw2[tid]; }
    sCw3[tid] = cw3[tid];
    __syncthreads();

    float acc[2][8][4];

    // ---------------- regression branch ----------------
    #pragma unroll 1
    for (int hg = 0; hg < 2; ++hg) {          // h1r = relu(X @ rw1^T + rb1) -> sH
        stage_w(g_wh + WR1 + hg * 32768, 128, sB, tid);
        __syncthreads();
        mma_block(sA, sB, acc, wm, wn, g, c2);
        epilogue_hidden(acc, rb1, hg * 128, sH, wm, wn, g, c2);
        __syncthreads();
    }
    #pragma unroll 1
    for (int hg = 0; hg < 2; ++hg) {          // h2r = relu(h1r @ rw2^T + rb2) -> sA
        stage_w(g_wh + WR2 + hg * 32768, 128, sB, tid);
        __syncthreads();
        mma_block(sH, sB, acc, wm, wn, g, c2);
        epilogue_hidden(acc, rb2, hg * 128, sA, wm, wn, g, c2);
        __syncthreads();
    }
    // reg_pred = h2r @ rw3^T + rb3 -> sReg (fp32) + global output
    stage_w(g_wh + WR3, R4, sB, tid);
    __syncthreads();
    mma_block(sA, sB, acc, wm, wn, g, c2);
    epilogue_reg(acc, rb3, sReg, out_reg, row0, wm, wn, g, c2);
    __syncthreads();

    // ---------------- per-position stats: softmax, box, top4 ----------------
    {
        int row = tid >> 1;
        int dbase = (tid & 1) * 2;
        #pragma unroll
        for (int dd = 0; dd < 2; ++dd) {
            int d = dbase + dd;
            const float* rp = sReg + row * R4 + d * NB;
            float pb[NB];
            float mx = -1e30f;
            #pragma unroll
            for (int b = 0; b < NB; ++b) { pb[b] = rp[b]; mx = fmaxf(mx, pb[b]); }
            float s = 0.f, sbi = 0.f;
            #pragma unroll
            for (int b = 0; b < NB; ++b) {
                float e = __expf(pb[b] - mx);
                pb[b] = e; s += e; sbi += e * (float)b;
            }
            float inv = 1.f / s;
            out_box[(size_t)(row0 + row) * 4 + d] = sbi * inv * (1.0f / 16.0f);
            unsigned mask = 0; float tsum = 0.f;
            #pragma unroll
            for (int j = 0; j < 4; ++j) {
                float m = -1e30f; int mi = 0;
                #pragma unroll
                for (int b = 0; b < NB; ++b) {
                    bool ok = !((mask >> b) & 1u) && (pb[b] > m);
                    if (ok) { m = pb[b]; mi = b; }
                }
                mask |= (1u << mi);
                tsum += m;
                sStat[row * 21 + d * 5 + j] = m * inv;
            }
            sStat[row * 21 + d * 5 + 4] = tsum * inv * 0.25f;
        }
    }
    __syncthreads();

    // quality = sigmoid(qw2 @ relu(qw1 @ stat + qb1) + qb2)
    if (tid < TM) {
        const float* st = sStat + tid * 21;
        float q = __ldg(qb2);
        #pragma unroll 4
        for (int o = 0; o < 64; ++o) {
            float h = sQb1[o];
            #pragma unroll
            for (int c = 0; c < 20; ++c) h += sQw1[o * 20 + c] * st[c];
            q += sQw2[o] * fmaxf(h, 0.f);
        }
        sQual[tid] = 1.f / (1.f + __expf(-q));
    }
    // reload X (sA held h2r, done with it)
    stage_x(x + (size_t)row0 * C, sA, tid);
    __syncthreads();

    // ---------------- classification branch ----------------
    #pragma unroll 1
    for (int hg = 0; hg < 2; ++hg) {          // h1c -> sH (sReg/sStat dead now)
        stage_w(g_wh + WC1 + hg * 32768, 128, sB, tid);
        __syncthreads();
        mma_block(sA, sB, acc, wm, wn, g, c2);
        epilogue_hidden(acc, cb1, hg * 128, sH, wm, wn, g, c2);
        __syncthreads();
    }
    #pragma unroll 1
    for (int hg = 0; hg < 2; ++hg) {          // h2c -> sA
        stage_w(g_wh + WC2 + hg * 32768, 128, sB, tid);
        __syncthreads();
        mma_block(sH, sB, acc, wm, wn, g, c2);
        epilogue_hidden(acc, cb2, hg * 128, sA, wm, wn, g, c2);
        __syncthreads();
    }
    // cls score = sigmoid(h2c . cw3 + cb3) * quality
    if (tid < TM) {
        const __half2* hrow = (const __half2*)sA + tid * (PITCH / 2);
        float a = __ldg(cb3);
        #pragma unroll 8
        for (int k = 0; k < 128; ++k) {
            float2 v = __half22float2(hrow[k]);
            a += v.x * sCw3[2 * k] + v.y * sCw3[2 * k + 1];
        }
        float csig = 1.f / (1.f + __expf(-a));
        out_cls[row0 + tid] = csig * sQual[tid];
    }
}

// ------------------------------ launcher -----------------------------------
extern "C" void kernel_launch(void* const* d_in, const int* in_sizes, int n_in,
                              void* d_out, int out_size) {
    const float* x   = (const float*)d_in[0];
    const float* cw1 = (const float*)d_in[1];
    const float* cb1 = (const float*)d_in[2];
    const float* cw2 = (const float*)d_in[3];
    const float* cb2 = (const float*)d_in[4];
    const float* cw3 = (const float*)d_in[5];
    const float* cb3 = (const float*)d_in[6];
    const float* rw1 = (const float*)d_in[7];
    const float* rb1 = (const float*)d_in[8];
    const float* rw2 = (const float*)d_in[9];
    const float* rb2 = (const float*)d_in[10];
    const float* rw3 = (const float*)d_in[11];
    const float* rb3 = (const float*)d_in[12];
    const float* qw1 = (const float*)d_in[13];
    const float* qb1 = (const float*)d_in[14];
    const float* qw2 = (const float*)d_in[15];
    const float* qb2 = (const float*)d_in[16];
    float* out = (float*)d_out;

    cudaFuncSetAttribute(gfocal_head_kernel,
                         cudaFuncAttributeMaxDynamicSharedMemorySize, cfg::SMEM_BYTES);

    convert_weights_kernel<<<(cfg::WTOT + 255) / 256, 256>>>(cw1, cw2, rw1, rw2, rw3);
    gfocal_head_kernel<<<cfg::NBLK, 256, cfg::SMEM_BYTES>>>(
        x, cb1, cb2, cw3, cb3, rb1, rb2, rb3, qw1, qb1, qw2, qb2, out);
}

// round 5
// speedup vs baseline: 1.1501x; 1.1424x over previous
#include <cuda_runtime.h>
#include <cuda_fp16.h>

#define DINL __device__ __forceinline__

// ---------------------------------------------------------------------------
// GFocalV2 head (sm_103 legacy tensor path): fused 3-layer MLPs via
// mma.sync.m16n8k16 fed by ldmatrix from SW128 blocked-atom smem, with
// cp.async double-buffered pre-swizzled weight streaming.
// ---------------------------------------------------------------------------

namespace cfg {
constexpr int P    = 32 * 96 * 96;   // 294912
constexpr int TM   = 128;            // rows per CTA
constexpr int NBLK = P / TM;         // 2304
constexpr int NCH  = 18;             // weight chunks: 64 out-rows x 256 in
constexpr int CHH  = 16384;          // halves per chunk (32 KB)

// dynamic smem (bytes)
constexpr int SA    = 0;             // 128x256 f16, blocked SW128 (64 KB)
constexpr int SH    = 65536;         // ping buffer / fp32 reg_pred alias
constexpr int SB    = 131072;        // 2 x 32768 weight buffers
constexpr int SBIAS = 196608;        // rb1 +0, rb2 +1024, cb1 +2048, cb2 +3072, rb3 +4096
constexpr int SSTAT = SBIAS + 4608;  // 128*21 f32 = 10752
constexpr int SQW1  = SSTAT + 10752; // 1280 f32
constexpr int SQB1  = SQW1 + 5120;   // 64 f32
constexpr int SQW2  = SQB1 + 256;    // 64 f32
constexpr int SCW3  = SQW2 + 256;    // 256 f32
constexpr int SQUAL = SCW3 + 1024;   // 128 f32
constexpr int SSC   = SQUAL + 512;   // [0]=qb2 [1]=cb3
constexpr int SMEMB = SSC + 16;      // 219168 B
}  // namespace cfg

__device__ __align__(16) __half g_wh[cfg::NCH * cfg::CHH];

// --------------------- weight fp32 -> fp16 pre-swizzled --------------------
// chunk = 64 out-rows x 256 cols; atom = 8 rows x 64 halves;
// atom_idx = (r>>3) + (c>>6)*8 ; byte = atom*1024 + (r&7)*128 + (c&63)*2
// byte ^= (r&7)<<4  (SW128)
__global__ void convert_weights_kernel(const float* __restrict__ cw1,
                                       const float* __restrict__ cw2,
                                       const float* __restrict__ rw1,
                                       const float* __restrict__ rw2,
                                       const float* __restrict__ rw3) {
    int i = blockIdx.x * 256 + threadIdx.x;   // 0..294911
    int ck = i >> 14;
    int e  = i & 16383;
    int r  = e >> 8, c = e & 255;
    float v = 0.f;
    if (ck < 4)        v = rw1[(ck * 64 + r) * 256 + c];
    else if (ck < 8)   v = rw2[((ck - 4) * 64 + r) * 256 + c];
    else if (ck < 10) { int gr = (ck - 8) * 64 + r; if (gr < 68) v = rw3[gr * 256 + c]; }
    else if (ck < 14)  v = cw1[((ck - 10) * 64 + r) * 256 + c];
    else               v = cw2[((ck - 14) * 64 + r) * 256 + c];
    int byte = ((r >> 3) + (c >> 6) * 8) * 1024 + (r & 7) * 128 + (c & 63) * 2;
    byte ^= (r & 7) << 4;
    g_wh[ck * cfg::CHH + (byte >> 1)] = __float2half(v);
}

// ------------------------------ PTX helpers --------------------------------
DINL unsigned smem_u32(const void* p) {
    unsigned a;
    asm("{ .reg .u64 t; cvta.to.shared.u64 t, %1; cvt.u32.u64 %0, t; }"
        : "=r"(a) : "l"(p));
    return a;
}
DINL void ldm4(unsigned r[4], unsigned addr) {
    asm volatile("ldmatrix.sync.aligned.m8n8.x4.shared.b16 {%0,%1,%2,%3}, [%4];"
                 : "=r"(r[0]), "=r"(r[1]), "=r"(r[2]), "=r"(r[3]) : "r"(addr));
}
DINL void mma4(float d[4], const unsigned a[4], unsigned b0, unsigned b1) {
    asm volatile(
        "mma.sync.aligned.m16n8k16.row.col.f32.f16.f16.f32 "
        "{%0,%1,%2,%3}, {%4,%5,%6,%7}, {%8,%9}, {%0,%1,%2,%3};\n"
        : "+f"(d[0]), "+f"(d[1]), "+f"(d[2]), "+f"(d[3])
        : "r"(a[0]), "r"(a[1]), "r"(a[2]), "r"(a[3]), "r"(b0), "r"(b1));
}
#define CP_COMMIT() asm volatile("cp.async.commit_group;" ::: "memory")
template <int N> DINL void cp_wait() {
    asm volatile("cp.async.wait_group %0;" :: "n"(N) : "memory");
}

// ----------------------------- staging -------------------------------------
DINL void stageW(int seq, unsigned sbm, int tid) {
    const __half* g = g_wh + (size_t)seq * cfg::CHH + tid * 8;
    unsigned dst = sbm + cfg::SB + (unsigned)((seq & 1) * 32768) + tid * 16;
    #pragma unroll
    for (int k = 0; k < 8; ++k)
        asm volatile("cp.async.cg.shared.global [%0], [%1], 16;"
                     :: "r"(dst + k * 4096), "l"(g + k * 2048) : "memory");
}

// 128 rows x 256 f32 -> f16 into sA, blocked SW128
DINL void stage_x(const float* __restrict__ x, char* smem, int tid) {
    #pragma unroll 4
    for (int i = tid; i < 4096; i += 256) {
        int r = i >> 5, u = i & 31;
        const float4* src = (const float4*)(x + (size_t)r * 256 + u * 8);
        float4 v0 = src[0], v1 = src[1];
        __half2 h0 = __floats2half2_rn(v0.x, v0.y);
        __half2 h1 = __floats2half2_rn(v0.z, v0.w);
        __half2 h2 = __floats2half2_rn(v1.x, v1.y);
        __half2 h3 = __floats2half2_rn(v1.z, v1.w);
        int byte = ((r >> 3) + (u >> 3) * 16) * 1024 + (r & 7) * 128 + (u & 7) * 16;
        byte ^= (r & 7) << 4;
        uint4 pk;
        pk.x = *(unsigned*)&h0; pk.y = *(unsigned*)&h1;
        pk.z = *(unsigned*)&h2; pk.w = *(unsigned*)&h3;
        *(uint4*)(smem + cfg::SA + byte) = pk;
    }
}

// chunk scheduler: sync; prefetch next chunk; wait current; sync; -> buffer
DINL unsigned chunk_step(int& seq, unsigned sbm, int tid) {
    __syncthreads();
    if (seq + 1 < cfg::NCH) {
        stageW(seq + 1, sbm, tid);
        CP_COMMIT();
        cp_wait<1>();
    } else {
        cp_wait<0>();
    }
    __syncthreads();
    unsigned b = sbm + cfg::SB + (unsigned)((seq & 1) * 32768);
    ++seq;
    return b;
}

// --------------------- 128x64 chunk GEMM via ldmatrix ----------------------
// warp (wm 0..3, wn 0..1): m32 (wm) x n32 (wn); NP=1 computes only nj 0,1.
template <int NP>
DINL void mma_chunk(unsigned aBase, unsigned bBase, float acc[2][4][4],
                    int lane, int wm, int wn) {
    #pragma unroll
    for (int i = 0; i < 2; ++i)
        #pragma unroll
        for (int j = 0; j < 4; ++j)
            #pragma unroll
            for (int k = 0; k < 4; ++k) acc[i][j][k] = 0.f;

    const int la7 = lane & 7, lb3 = (lane >> 3) & 1, lb4 = (lane >> 4) & 1;
    // row bases (swizzle handled per-k via unit XOR with la7)
    unsigned rowA[2], rowB[2];
    #pragma unroll
    for (int mi = 0; mi < 2; ++mi) {
        int R = wm * 32 + mi * 16 + lb3 * 8 + la7;
        rowA[mi] = aBase + (unsigned)((R >> 3) * 1024 + la7 * 128);
    }
    #pragma unroll
    for (int np = 0; np < 2; ++np) {
        int R = wn * 32 + np * 16 + lb4 * 8 + la7;
        rowB[np] = bBase + (unsigned)((R >> 3) * 1024 + la7 * 128);
    }
    #pragma unroll
    for (int k0 = 0; k0 < 16; ++k0) {
        int qa = 2 * k0 + lb4, qb = 2 * k0 + lb3;
        unsigned ca = (unsigned)(((qa >> 3) << 14) + (((qa & 7) ^ la7) << 4));
        unsigned cb = (unsigned)(((qb >> 3) << 13) + (((qb & 7) ^ la7) << 4));
        unsigned a0[4], a1[4], b0[4];
        ldm4(a0, rowA[0] + ca);
        ldm4(a1, rowA[1] + ca);
        ldm4(b0, rowB[0] + cb);
        mma4(acc[0][0], a0, b0[0], b0[1]);
        mma4(acc[0][1], a0, b0[2], b0[3]);
        mma4(acc[1][0], a1, b0[0], b0[1]);
        mma4(acc[1][1], a1, b0[2], b0[3]);
        if (NP == 2) {
            unsigned b1[4];
            ldm4(b1, rowB[1] + cb);
            mma4(acc[0][2], a0, b1[0], b1[1]);
            mma4(acc[0][3], a0, b1[2], b1[3]);
            mma4(acc[1][2], a1, b1[0], b1[1]);
            mma4(acc[1][3], a1, b1[2], b1[3]);
        }
    }
}

// bias + relu -> f16 into blocked SW128 tile
DINL void epi_hidden(const float acc[2][4][4], char* sOut, const float* bias,
                     int cbase, int lane, int wm, int wn) {
    #pragma unroll
    for (int mi = 0; mi < 2; ++mi) {
        int R = wm * 32 + mi * 16 + (lane >> 2);
        #pragma unroll
        for (int nj = 0; nj < 4; ++nj) {
            int C = cbase + wn * 32 + nj * 8 + (lane & 3) * 2;
            float b0 = bias[C], b1 = bias[C + 1];
            __half2 lo = __floats2half2_rn(fmaxf(acc[mi][nj][0] + b0, 0.f),
                                           fmaxf(acc[mi][nj][1] + b1, 0.f));
            __half2 hi = __floats2half2_rn(fmaxf(acc[mi][nj][2] + b0, 0.f),
                                           fmaxf(acc[mi][nj][3] + b1, 0.f));
            int byte = ((R >> 3) + (C >> 6) * 16) * 1024 + (R & 7) * 128 + (C & 63) * 2;
            byte ^= (R & 7) << 4;
            *(__half2*)(sOut + byte) = lo;
            *(__half2*)(sOut + byte + 1024) = hi;   // row R+8: atom+1, same swizzle
        }
    }
}

// reg-pred epilogue: fp32 to sReg (stride 68) + global
DINL void epi_reg(const float acc[2][4][4], float* sReg, const float* bias,
                  float* __restrict__ gReg, int row0, int cbase,
                  int lane, int wm, int wn, int njlim) {
    #pragma unroll
    for (int mi = 0; mi < 2; ++mi) {
        int R = wm * 32 + mi * 16 + (lane >> 2);
        #pragma unroll
        for (int nj = 0; nj < 4; ++nj) {
            if (nj >= njlim) break;
            int C = cbase + wn * 32 + nj * 8 + (lane & 3) * 2;
            if (C < 68) {
                float b0 = bias[C], b1 = bias[C + 1];
                float2 lo = make_float2(acc[mi][nj][0] + b0, acc[mi][nj][1] + b1);
                float2 hi = make_float2(acc[mi][nj][2] + b0, acc[mi][nj][3] + b1);
                *(float2*)(sReg + R * 68 + C) = lo;
                *(float2*)(sReg + (R + 8) * 68 + C) = hi;
                *(float2*)(gReg + (size_t)(row0 + R) * 68 + C) = lo;
                *(float2*)(gReg + (size_t)(row0 + R + 8) * 68 + C) = hi;
            }
        }
    }
}

// ------------------------------ main kernel --------------------------------
__global__ __launch_bounds__(256, 1)
void gfocal_head_kernel(const float* __restrict__ x,
                        const float* __restrict__ cb1, const float* __restrict__ cb2,
                        const float* __restrict__ cw3, const float* __restrict__ cb3,
                        const float* __restrict__ rb1, const float* __restrict__ rb2,
                        const float* __restrict__ rb3,
                        const float* __restrict__ qw1, const float* __restrict__ qb1,
                        const float* __restrict__ qw2, const float* __restrict__ qb2,
                        float* __restrict__ out) {
    using namespace cfg;
    extern __shared__ char smem[];
    const unsigned sbm = smem_u32(smem);
    const int tid = threadIdx.x, w = tid >> 5, lane = tid & 31;
    const int wm = w >> 1, wn = w & 1;
    const int row0 = blockIdx.x * TM;

    float* out_cls = out;
    float* out_box = out + (size_t)P;
    float* out_reg = out + (size_t)P * 5;

    const float* bias = (const float*)(smem + SBIAS);

    // ---- prolog: small weights, stage X, prefetch chunk 0 ----
    {
        float* fb = (float*)(smem + SBIAS);
        fb[tid] = rb1[tid]; fb[256 + tid] = rb2[tid];
        fb[512 + tid] = cb1[tid]; fb[768 + tid] = cb2[tid];
        if (tid < 68) fb[1024 + tid] = rb3[tid];
        ((float*)(smem + SCW3))[tid] = cw3[tid];
        float* q1 = (float*)(smem + SQW1);
        for (int i = tid; i < 1280; i += 256) q1[i] = qw1[i];
        if (tid < 64) { ((float*)(smem + SQB1))[tid] = qb1[tid];
                        ((float*)(smem + SQW2))[tid] = qw2[tid]; }
        if (tid == 0) { ((float*)(smem + SSC))[0] = qb2[0];
                        ((float*)(smem + SSC))[1] = cb3[0]; }
    }
    stageW(0, sbm, tid);
    CP_COMMIT();
    stage_x(x + (size_t)row0 * 256, smem, tid);

    int seq = 0;
    float acc[2][4][4];

    // ---------------- regression branch ----------------
    #pragma unroll 1
    for (int c = 0; c < 4; ++c) {                       // X @ rw1^T -> SH
        unsigned bb = chunk_step(seq, sbm, tid);
        mma_chunk<2>(sbm + SA, bb, acc, lane, wm, wn);
        epi_hidden(acc, smem + SH, bias, c * 64, lane, wm, wn);
    }
    #pragma unroll 1
    for (int c = 0; c < 4; ++c) {                       // h1 @ rw2^T -> SA
        unsigned bb = chunk_step(seq, sbm, tid);
        mma_chunk<2>(sbm + SH, bb, acc, lane, wm, wn);
        epi_hidden(acc, smem + SA, bias + 256, c * 64, lane, wm, wn);
    }
    {                                                   // reg_pred cols 0..63
        unsigned bb = chunk_step(seq, sbm, tid);
        mma_chunk<2>(sbm + SA, bb, acc, lane, wm, wn);
        epi_reg(acc, (float*)(smem + SH), bias + 1024, out_reg, row0, 0,
                lane, wm, wn, 4);
    }
    {                                                   // reg_pred cols 64..67
        unsigned bb = chunk_step(seq, sbm, tid);
        if (wn == 0) {
            mma_chunk<1>(sbm + SA, bb, acc, lane, wm, wn);
            epi_reg(acc, (float*)(smem + SH), bias + 1024, out_reg, row0, 64,
                    lane, wm, wn, 2);
        }
    }
    __syncthreads();

    // ---- stats: softmax, box, top-4 -> sStat ----
    {
        int row = tid >> 1;
        int dbase = (tid & 1) * 2;
        const float* sReg = (const float*)(smem + SH);
        float* sStat = (float*)(smem + SSTAT);
        #pragma unroll
        for (int dd = 0; dd < 2; ++dd) {
            int d = dbase + dd;
            const float* rp = sReg + row * 68 + d * 17;
            float pb[17];
            float mx = -1e30f;
            #pragma unroll
            for (int b = 0; b < 17; ++b) { pb[b] = rp[b]; mx = fmaxf(mx, pb[b]); }
            float s = 0.f, sbi = 0.f;
            #pragma unroll
            for (int b = 0; b < 17; ++b) {
                float e = __expf(pb[b] - mx);
                pb[b] = e; s += e; sbi += e * (float)b;
            }
            float inv = 1.f / s;
            out_box[(size_t)(row0 + row) * 4 + d] = sbi * inv * (1.f / 16.f);
            unsigned mask = 0; float tsum = 0.f;
            #pragma unroll
            for (int j = 0; j < 4; ++j) {
                float m = -1e30f; int mi = 0;
                #pragma unroll
                for (int b = 0; b < 17; ++b) {
                    bool ok = !((mask >> b) & 1u) && (pb[b] > m);
                    if (ok) { m = pb[b]; mi = b; }
                }
                mask |= (1u << mi);
                tsum += m;
                sStat[row * 21 + d * 5 + j] = m * inv;
            }
            sStat[row * 21 + d * 5 + 4] = tsum * inv * 0.25f;
        }
    }
    __syncthreads();

    // ---- quality (tid<128) + restage X for cls (all threads) ----
    if (tid < TM) {
        const float* st = (const float*)(smem + SSTAT) + tid * 21;
        const float* q1 = (const float*)(smem + SQW1);
        const float* qb = (const float*)(smem + SQB1);
        const float* q2 = (const float*)(smem + SQW2);
        float q = ((const float*)(smem + SSC))[0];
        #pragma unroll 4
        for (int o = 0; o < 64; ++o) {
            float h = qb[o];
            #pragma unroll
            for (int c = 0; c < 20; ++c) h += q1[o * 20 + c] * st[c];
            q += q2[o] * fmaxf(h, 0.f);
        }
        ((float*)(smem + SQUAL))[tid] = 1.f / (1.f + __expf(-q));
    }
    stage_x(x + (size_t)row0 * 256, smem, tid);

    // ---------------- classification branch ----------------
    #pragma unroll 1
    for (int c = 0; c < 4; ++c) {                       // X @ cw1^T -> SH
        unsigned bb = chunk_step(seq, sbm, tid);
        mma_chunk<2>(sbm + SA, bb, acc, lane, wm, wn);
        epi_hidden(acc, smem + SH, bias + 512, c * 64, lane, wm, wn);
    }
    #pragma unroll 1
    for (int c = 0; c < 4; ++c) {                       // h1 @ cw2^T -> SA
        unsigned bb = chunk_step(seq, sbm, tid);
        mma_chunk<2>(sbm + SH, bb, acc, lane, wm, wn);
        epi_hidden(acc, smem + SA, bias + 768, c * 64, lane, wm, wn);
    }
    __syncthreads();

    // ---- cls L3: dot(h2c, cw3) + cb3, sigmoid, * quality ----
    if (tid < TM) {
        int r = tid, r7 = r & 7;
        unsigned rbase = (unsigned)((r >> 3) * 1024 + r7 * 128);
        const float* w3 = (const float*)(smem + SCW3);
        float a = ((const float*)(smem + SSC))[1];
        #pragma unroll
        for (int cg = 0; cg < 4; ++cg) {
            #pragma unroll
            for (int u = 0; u < 8; ++u) {
                const __half2* p = (const __half2*)(smem + SA + rbase +
                                                    cg * 16384 + ((u ^ r7) << 4));
                const float* wseg = w3 + cg * 64 + u * 8;
                #pragma unroll
                for (int j = 0; j < 4; ++j) {
                    float2 v = __half22float2(p[j]);
                    a += v.x * wseg[2 * j] + v.y * wseg[2 * j + 1];
                }
            }
        }
        float csig = 1.f / (1.f + __expf(-a));
        out_cls[row0 + r] = csig * ((const float*)(smem + SQUAL))[r];
    }
}

// ------------------------------ launcher -----------------------------------
extern "C" void kernel_launch(void* const* d_in, const int* in_sizes, int n_in,
                              void* d_out, int out_size) {
    const float* x   = (const float*)d_in[0];
    const float* cw1 = (const float*)d_in[1];
    const float* cb1 = (const float*)d_in[2];
    const float* cw2 = (const float*)d_in[3];
    const float* cb2 = (const float*)d_in[4];
    const float* cw3 = (const float*)d_in[5];
    const float* cb3 = (const float*)d_in[6];
    const float* rw1 = (const float*)d_in[7];
    const float* rb1 = (const float*)d_in[8];
    const float* rw2 = (const float*)d_in[9];
    const float* rb2 = (const float*)d_in[10];
    const float* rw3 = (const float*)d_in[11];
    const float* rb3 = (const float*)d_in[12];
    const float* qw1 = (const float*)d_in[13];
    const float* qb1 = (const float*)d_in[14];
    const float* qw2 = (const float*)d_in[15];
    const float* qb2 = (const float*)d_in[16];
    float* out = (float*)d_out;

    cudaFuncSetAttribute(gfocal_head_kernel,
                         cudaFuncAttributeMaxDynamicSharedMemorySize, cfg::SMEMB);

    convert_weights_kernel<<<cfg::NCH * cfg::CHH / 256, 256>>>(cw1, cw2, rw1, rw2, rw3);
    gfocal_head_kernel<<<cfg::NBLK, 256, cfg::SMEMB>>>(
        x, cb1, cb2, cw3, cb3, rb1, rb2, rb3, qw1, qb1, qw2, qb2, out);
}

// round 6
// speedup vs baseline: 1.2368x; 1.0754x over previous
#include <cuda_runtime.h>
#include <cuda_fp16.h>

#define DINL __device__ __forceinline__

// ---------------------------------------------------------------------------
// GFocalV2 head (sm_103): fused 3-layer MLPs via mma.sync.m16n8k16 + ldmatrix
// from SW128 blocked-atom smem. 512 threads / 16 warps, 128x128 weight
// superchunks (single 64KB buffer), pre-swizzled fp16 weight cache.
// ---------------------------------------------------------------------------

namespace cfg {
constexpr int P    = 32 * 96 * 96;   // 294912
constexpr int TM   = 128;            // rows per CTA
constexpr int NBLK = P / TM;         // 2304
constexpr int NSC  = 9;              // superchunks: 128 out-rows x 256 in
constexpr int SCH  = 32768;          // halves per superchunk (64 KB)

// dynamic smem (bytes)
constexpr int SA    = 0;             // 128x256 f16 blocked SW128 (64 KB)
constexpr int SH    = 65536;         // ping buffer / fp32 reg_pred alias
constexpr int SB    = 131072;        // 64 KB weight superchunk
constexpr int SBIAS = 196608;        // rb1 +0, rb2 +1024, cb1 +2048, cb2 +3072, rb3 +4096
constexpr int SSTAT = SBIAS + 4608;  // 128*21 f32
constexpr int SQW1  = SSTAT + 10752;
constexpr int SQB1  = SQW1 + 5120;
constexpr int SQW2  = SQB1 + 256;
constexpr int SCW3  = SQW2 + 256;
constexpr int SQUAL = SCW3 + 1024;
constexpr int SSC   = SQUAL + 512;
constexpr int SMEMB = SSC + 16;      // 219168 B
}  // namespace cfg

__device__ __align__(16) __half g_wh[cfg::NSC * cfg::SCH];

// --------------------- weight fp32 -> fp16 pre-swizzled --------------------
// superchunk = 128 out-rows x 256 cols; atom = 8 rows x 64 halves;
// atom = (r>>3) + (c>>6)*16 ; byte = atom*1024 + (r&7)*128 + (c&63)*2 ; ^(r&7)<<4
__global__ void convert_weights_kernel(const float* __restrict__ cw1,
                                       const float* __restrict__ cw2,
                                       const float* __restrict__ rw1,
                                       const float* __restrict__ rw2,
                                       const float* __restrict__ rw3) {
    int i = blockIdx.x * 512 + threadIdx.x;   // 0..294911
    int sc = i >> 15;
    int e  = i & 32767;
    int r  = e >> 8, c = e & 255;
    float v = 0.f;
    if (sc < 2)       v = rw1[(sc * 128 + r) * 256 + c];
    else if (sc < 4)  v = rw2[((sc - 2) * 128 + r) * 256 + c];
    else if (sc < 5)  { if (r < 68) v = rw3[r * 256 + c]; }
    else if (sc < 7)  v = cw1[((sc - 5) * 128 + r) * 256 + c];
    else              v = cw2[((sc - 7) * 128 + r) * 256 + c];
    int byte = ((r >> 3) + (c >> 6) * 16) * 1024 + (r & 7) * 128 + (c & 63) * 2;
    byte ^= (r & 7) << 4;
    g_wh[sc * cfg::SCH + (byte >> 1)] = __float2half(v);
}

// ------------------------------ PTX helpers --------------------------------
DINL unsigned smem_u32(const void* p) {
    unsigned a;
    asm("{ .reg .u64 t; cvta.to.shared.u64 t, %1; cvt.u32.u64 %0, t; }"
        : "=r"(a) : "l"(p));
    return a;
}
DINL void ldm4(unsigned r[4], unsigned addr) {
    asm volatile("ldmatrix.sync.aligned.m8n8.x4.shared.b16 {%0,%1,%2,%3}, [%4];"
                 : "=r"(r[0]), "=r"(r[1]), "=r"(r[2]), "=r"(r[3]) : "r"(addr));
}
DINL void mma4(float d[4], const unsigned a[4], unsigned b0, unsigned b1) {
    asm volatile(
        "mma.sync.aligned.m16n8k16.row.col.f32.f16.f16.f32 "
        "{%0,%1,%2,%3}, {%4,%5,%6,%7}, {%8,%9}, {%0,%1,%2,%3};\n"
        : "+f"(d[0]), "+f"(d[1]), "+f"(d[2]), "+f"(d[3])
        : "r"(a[0]), "r"(a[1]), "r"(a[2]), "r"(a[3]), "r"(b0), "r"(b1));
}
#define CP_COMMIT() asm volatile("cp.async.commit_group;" ::: "memory")
template <int N> DINL void cp_wait() {
    asm volatile("cp.async.wait_group %0;" :: "n"(N) : "memory");
}

// ----------------------------- staging -------------------------------------
// 64 KB superchunk: 512 threads x 8 x 16B
DINL void stageW(int sc, unsigned sbm, int tid) {
    const __half* g = g_wh + (size_t)sc * cfg::SCH + tid * 8;
    unsigned dst = sbm + cfg::SB + tid * 16;
    #pragma unroll
    for (int k = 0; k < 8; ++k)
        asm volatile("cp.async.cg.shared.global [%0], [%1], 16;"
                     :: "r"(dst + k * 8192), "l"(g + k * 4096) : "memory");
}

// 128 rows x 256 f32 -> f16 into tile, blocked SW128 (512 threads)
DINL void stage_x(const float* __restrict__ x, char* smem, int tid) {
    #pragma unroll
    for (int i = tid; i < 4096; i += 512) {
        int r = i >> 5, u = i & 31;
        const float4* src = (const float4*)(x + (size_t)r * 256 + u * 8);
        float4 v0 = src[0], v1 = src[1];
        __half2 h0 = __floats2half2_rn(v0.x, v0.y);
        __half2 h1 = __floats2half2_rn(v0.z, v0.w);
        __half2 h2 = __floats2half2_rn(v1.x, v1.y);
        __half2 h3 = __floats2half2_rn(v1.z, v1.w);
        int byte = ((r >> 3) + (u >> 3) * 16) * 1024 + (r & 7) * 128 + (u & 7) * 16;
        byte ^= (r & 7) << 4;
        uint4 pk;
        pk.x = *(unsigned*)&h0; pk.y = *(unsigned*)&h1;
        pk.z = *(unsigned*)&h2; pk.w = *(unsigned*)&h3;
        *(uint4*)(smem + cfg::SA + byte) = pk;
    }
}

// superchunk scheduler: sync (prev consumers done), stage, wait, sync
DINL void chunk_step(int sc, unsigned sbm, int tid) {
    __syncthreads();
    stageW(sc, sbm, tid);
    CP_COMMIT();
    cp_wait<0>();
    __syncthreads();
}

// ---------------- 128x128 superchunk GEMM via ldmatrix ---------------------
// 16 warps: wm 0..3 (32 rows), wn 0..3 (32 cols). A and B tiles share the
// 128x256 blocked-atom SW128 layout (atom-group stride 16 KB).
DINL void mma_chunk(unsigned aBase, unsigned bBase, float acc[2][4][4],
                    int lane, int wm, int wn) {
    #pragma unroll
    for (int i = 0; i < 2; ++i)
        #pragma unroll
        for (int j = 0; j < 4; ++j)
            #pragma unroll
            for (int k = 0; k < 4; ++k) acc[i][j][k] = 0.f;

    const int la7 = lane & 7, lb3 = (lane >> 3) & 1, lb4 = (lane >> 4) & 1;
    unsigned rowA[2], rowB[2];
    #pragma unroll
    for (int mi = 0; mi < 2; ++mi) {
        int R = wm * 32 + mi * 16 + lb3 * 8 + la7;
        rowA[mi] = aBase + (unsigned)((R >> 3) * 1024 + la7 * 128);
    }
    #pragma unroll
    for (int np = 0; np < 2; ++np) {
        int R = wn * 32 + np * 16 + lb4 * 8 + la7;
        rowB[np] = bBase + (unsigned)((R >> 3) * 1024 + la7 * 128);
    }
    #pragma unroll
    for (int k0 = 0; k0 < 16; ++k0) {
        int qa = 2 * k0 + lb4, qb = 2 * k0 + lb3;
        unsigned ca = (unsigned)(((qa >> 3) << 14) + (((qa & 7) ^ la7) << 4));
        unsigned cb = (unsigned)(((qb >> 3) << 14) + (((qb & 7) ^ la7) << 4));
        unsigned a0[4], a1[4], b0[4], b1[4];
        ldm4(a0, rowA[0] + ca);
        ldm4(a1, rowA[1] + ca);
        ldm4(b0, rowB[0] + cb);
        ldm4(b1, rowB[1] + cb);
        mma4(acc[0][0], a0, b0[0], b0[1]);
        mma4(acc[0][1], a0, b0[2], b0[3]);
        mma4(acc[1][0], a1, b0[0], b0[1]);
        mma4(acc[1][1], a1, b0[2], b0[3]);
        mma4(acc[0][2], a0, b1[0], b1[1]);
        mma4(acc[0][3], a0, b1[2], b1[3]);
        mma4(acc[1][2], a1, b1[0], b1[1]);
        mma4(acc[1][3], a1, b1[2], b1[3]);
    }
}

// bias + relu -> f16 into blocked SW128 tile (cbase = 0 or 128)
DINL void epi_hidden(const float acc[2][4][4], char* sOut, const float* bias,
                     int cbase, int lane, int wm, int wn) {
    #pragma unroll
    for (int mi = 0; mi < 2; ++mi) {
        int R = wm * 32 + mi * 16 + (lane >> 2);
        #pragma unroll
        for (int nj = 0; nj < 4; ++nj) {
            int C = cbase + wn * 32 + nj * 8 + (lane & 3) * 2;
            float b0 = bias[C], b1 = bias[C + 1];
            __half2 lo = __floats2half2_rn(fmaxf(acc[mi][nj][0] + b0, 0.f),
                                           fmaxf(acc[mi][nj][1] + b1, 0.f));
            __half2 hi = __floats2half2_rn(fmaxf(acc[mi][nj][2] + b0, 0.f),
                                           fmaxf(acc[mi][nj][3] + b1, 0.f));
            int byte = ((R >> 3) + (C >> 6) * 16) * 1024 + (R & 7) * 128 + (C & 63) * 2;
            byte ^= (R & 7) << 4;
            *(__half2*)(sOut + byte) = lo;
            *(__half2*)(sOut + byte + 1024) = hi;   // row R+8: next atom
        }
    }
}

// reg-pred epilogue: fp32 (cols < 68) to sReg (stride 68) + global
DINL void epi_reg(const float acc[2][4][4], float* sReg, const float* bias,
                  float* __restrict__ gReg, int row0, int lane, int wm, int wn) {
    #pragma unroll
    for (int mi = 0; mi < 2; ++mi) {
        int R = wm * 32 + mi * 16 + (lane >> 2);
        #pragma unroll
        for (int nj = 0; nj < 4; ++nj) {
            int C = wn * 32 + nj * 8 + (lane & 3) * 2;
            if (C < 68) {
                float b0 = bias[C], b1 = bias[C + 1];
                float2 lo = make_float2(acc[mi][nj][0] + b0, acc[mi][nj][1] + b1);
                float2 hi = make_float2(acc[mi][nj][2] + b0, acc[mi][nj][3] + b1);
                *(float2*)(sReg + R * 68 + C) = lo;
                *(float2*)(sReg + (R + 8) * 68 + C) = hi;
                *(float2*)(gReg + (size_t)(row0 + R) * 68 + C) = lo;
                *(float2*)(gReg + (size_t)(row0 + R + 8) * 68 + C) = hi;
            }
        }
    }
}

// ------------------------------ main kernel --------------------------------
__global__ __launch_bounds__(512, 1)
void gfocal_head_kernel(const float* __restrict__ x,
                        const float* __restrict__ cb1, const float* __restrict__ cb2,
                        const float* __restrict__ cw3, const float* __restrict__ cb3,
                        const float* __restrict__ rb1, const float* __restrict__ rb2,
                        const float* __restrict__ rb3,
                        const float* __restrict__ qw1, const float* __restrict__ qb1,
                        const float* __restrict__ qw2, const float* __restrict__ qb2,
                        float* __restrict__ out) {
    using namespace cfg;
    extern __shared__ char smem[];
    const unsigned sbm = smem_u32(smem);
    const int tid = threadIdx.x, w = tid >> 5, lane = tid & 31;
    const int wm = w >> 2, wn = w & 3;
    const int row0 = blockIdx.x * TM;

    float* out_cls = out;
    float* out_box = out + (size_t)P;
    float* out_reg = out + (size_t)P * 5;

    const float* bias = (const float*)(smem + SBIAS);

    // ---- prolog: small weights, stage X ----
    if (tid < 256) {
        float* fb = (float*)(smem + SBIAS);
        fb[tid] = rb1[tid]; fb[256 + tid] = rb2[tid];
        fb[512 + tid] = cb1[tid]; fb[768 + tid] = cb2[tid];
        if (tid < 68) fb[1024 + tid] = rb3[tid];
        ((float*)(smem + SCW3))[tid] = cw3[tid];
        if (tid < 64) { ((float*)(smem + SQB1))[tid] = qb1[tid];
                        ((float*)(smem + SQW2))[tid] = qw2[tid]; }
        if (tid == 0) { ((float*)(smem + SSC))[0] = qb2[0];
                        ((float*)(smem + SSC))[1] = cb3[0]; }
    }
    {
        float* q1 = (float*)(smem + SQW1);
        for (int i = tid; i < 1280; i += 512) q1[i] = qw1[i];
    }
    stage_x(x + (size_t)row0 * 256, smem, tid);

    float acc[2][4][4];

    // ---------------- regression branch ----------------
    #pragma unroll 1
    for (int c = 0; c < 2; ++c) {                       // X @ rw1^T -> SH
        chunk_step(c, sbm, tid);
        mma_chunk(sbm + SA, sbm + SB, acc, lane, wm, wn);
        epi_hidden(acc, smem + SH, bias, c * 128, lane, wm, wn);
    }
    #pragma unroll 1
    for (int c = 0; c < 2; ++c) {                       // h1 @ rw2^T -> SA
        chunk_step(2 + c, sbm, tid);
        mma_chunk(sbm + SH, sbm + SB, acc, lane, wm, wn);
        epi_hidden(acc, smem + SA, bias + 256, c * 128, lane, wm, wn);
    }
    {                                                   // reg_pred (68 cols)
        chunk_step(4, sbm, tid);
        mma_chunk(sbm + SA, sbm + SB, acc, lane, wm, wn);
        epi_reg(acc, (float*)(smem + SH), bias + 1024, out_reg, row0, lane, wm, wn);
    }
    __syncthreads();

    // ---- stats: softmax, box, top-4 -> sStat (thread = (row, direction)) ----
    {
        int row = tid >> 2, d = tid & 3;
        const float* rp = (const float*)(smem + SH) + row * 68 + d * 17;
        float* sStat = (float*)(smem + SSTAT);
        float pb[17];
        float mx = -1e30f;
        #pragma unroll
        for (int b = 0; b < 17; ++b) { pb[b] = rp[b]; mx = fmaxf(mx, pb[b]); }
        float s = 0.f, sbi = 0.f;
        #pragma unroll
        for (int b = 0; b < 17; ++b) {
            float e = __expf(pb[b] - mx);
            pb[b] = e; s += e; sbi += e * (float)b;
        }
        float inv = 1.f / s;
        out_box[(size_t)(row0 + row) * 4 + d] = sbi * inv * (1.f / 16.f);
        unsigned mask = 0; float tsum = 0.f;
        #pragma unroll
        for (int j = 0; j < 4; ++j) {
            float m = -1e30f; int mi = 0;
            #pragma unroll
            for (int b = 0; b < 17; ++b) {
                bool ok = !((mask >> b) & 1u) && (pb[b] > m);
                if (ok) { m = pb[b]; mi = b; }
            }
            mask |= (1u << mi);
            tsum += m;
            sStat[row * 21 + d * 5 + j] = m * inv;
        }
        sStat[row * 21 + d * 5 + 4] = tsum * inv * 0.25f;
    }
    __syncthreads();

    // ---- quality (tid<128) + restage X for cls (all threads) ----
    if (tid < TM) {
        const float* st = (const float*)(smem + SSTAT) + tid * 21;
        const float* q1 = (const float*)(smem + SQW1);
        const float* qb = (const float*)(smem + SQB1);
        const float* q2 = (const float*)(smem + SQW2);
        float q = ((const float*)(smem + SSC))[0];
        #pragma unroll 4
        for (int o = 0; o < 64; ++o) {
            float h = qb[o];
            #pragma unroll
            for (int c = 0; c < 20; ++c) h += q1[o * 20 + c] * st[c];
            q += q2[o] * fmaxf(h, 0.f);
        }
        ((float*)(smem + SQUAL))[tid] = 1.f / (1.f + __expf(-q));
    }
    stage_x(x + (size_t)row0 * 256, smem, tid);

    // ---------------- classification branch ----------------
    #pragma unroll 1
    for (int c = 0; c < 2; ++c) {                       // X @ cw1^T -> SH
        chunk_step(5 + c, sbm, tid);
        mma_chunk(sbm + SA, sbm + SB, acc, lane, wm, wn);
        epi_hidden(acc, smem + SH, bias + 512, c * 128, lane, wm, wn);
    }
    #pragma unroll 1
    for (int c = 0; c < 2; ++c) {                       // h1 @ cw2^T -> SA
        chunk_step(7 + c, sbm, tid);
        mma_chunk(sbm + SH, sbm + SB, acc, lane, wm, wn);
        epi_hidden(acc, smem + SA, bias + 768, c * 128, lane, wm, wn);
    }
    __syncthreads();

    // ---- cls L3: dot(h2c, cw3) + cb3, sigmoid, * quality ----
    if (tid < TM) {
        int r = tid, r7 = r & 7;
        unsigned rbase = (unsigned)((r >> 3) * 1024 + r7 * 128);
        const float* w3 = (const float*)(smem + SCW3);
        float a = ((const float*)(smem + SSC))[1];
        #pragma unroll
        for (int cg = 0; cg < 4; ++cg) {
            #pragma unroll
            for (int u = 0; u < 8; ++u) {
                const __half2* p = (const __half2*)(smem + SA + rbase +
                                                    cg * 16384 + ((u ^ r7) << 4));
                const float* wseg = w3 + cg * 64 + u * 8;
                #pragma unroll
                for (int j = 0; j < 4; ++j) {
                    float2 v = __half22float2(p[j]);
                    a += v.x * wseg[2 * j] + v.y * wseg[2 * j + 1];
                }
            }
        }
        float csig = 1.f / (1.f + __expf(-a));
        out_cls[row0 + r] = csig * ((const float*)(smem + SQUAL))[r];
    }
}

// ------------------------------ launcher -----------------------------------
extern "C" void kernel_launch(void* const* d_in, const int* in_sizes, int n_in,
                              void* d_out, int out_size) {
    const float* x   = (const float*)d_in[0];
    const float* cw1 = (const float*)d_in[1];
    const float* cb1 = (const float*)d_in[2];
    const float* cw2 = (const float*)d_in[3];
    const float* cb2 = (const float*)d_in[4];
    const float* cw3 = (const float*)d_in[5];
    const float* cb3 = (const float*)d_in[6];
    const float* rw1 = (const float*)d_in[7];
    const float* rb1 = (const float*)d_in[8];
    const float* rw2 = (const float*)d_in[9];
    const float* rb2 = (const float*)d_in[10];
    const float* rw3 = (const float*)d_in[11];
    const float* rb3 = (const float*)d_in[12];
    const float* qw1 = (const float*)d_in[13];
    const float* qb1 = (const float*)d_in[14];
    const float* qw2 = (const float*)d_in[15];
    const float* qb2 = (const float*)d_in[16];
    float* out = (float*)d_out;

    cudaFuncSetAttribute(gfocal_head_kernel,
                         cudaFuncAttributeMaxDynamicSharedMemorySize, cfg::SMEMB);

    convert_weights_kernel<<<cfg::NSC * cfg::SCH / 512, 512>>>(cw1, cw2, rw1, rw2, rw3);
    gfocal_head_kernel<<<cfg::NBLK, 512, cfg::SMEMB>>>(
        x, cb1, cb2, cw3, cb3, rb1, rb2, rb3, qw1, qb1, qw2, qb2, out);
}

// round 7
// speedup vs baseline: 1.3018x; 1.0525x over previous
#include <cuda_runtime.h>
#include <cuda_fp16.h>

#define DINL __device__ __forceinline__

// ---------------------------------------------------------------------------
// GFocalV2 head (sm_103): fused 3-layer MLPs via mma.sync.m16n8k16 + ldmatrix
// from SW128 blocked-atom smem. 512 threads / 16 warps. Weights streamed as
// 18 x 32KB K-halves, double-buffered cp.async hidden under MMA.
// ---------------------------------------------------------------------------

namespace cfg {
constexpr int P    = 32 * 96 * 96;   // 294912
constexpr int TM   = 128;            // rows per CTA
constexpr int NBLK = P / TM;         // 2304
constexpr int NH   = 18;             // 32KB K-half chunks
constexpr int HHALF = 16384;         // halves per half-chunk

// dynamic smem (bytes)
constexpr int SA    = 0;             // 128x256 f16 blocked SW128 (64 KB)
constexpr int SH    = 65536;         // ping buffer / fp32 reg_pred alias
constexpr int SB    = 131072;        // 2 x 32KB weight half-buffers
constexpr int SBIAS = 196608;        // rb1 +0, rb2 +1024, cb1 +2048, cb2 +3072, rb3 +4096
constexpr int SSTAT = SBIAS + 4608;  // 128*21 f32
constexpr int SQW1  = SSTAT + 10752;
constexpr int SQB1  = SQW1 + 5120;
constexpr int SQW2  = SQB1 + 256;
constexpr int SCW3  = SQW2 + 256;
constexpr int SQUAL = SCW3 + 1024;
constexpr int SSC   = SQUAL + 512;
constexpr int SMEMB = SSC + 16;      // 219168 B
}  // namespace cfg

__device__ __align__(16) __half g_wh[cfg::NH * cfg::HHALF];

// --------------------- weight fp32 -> fp16 pre-swizzled --------------------
// superchunk sc = 128 out-rows x 256 cols; atom = 8 rows x 64 halves;
// atom = (r>>3) + (c>>6)*16 ; byte = atom*1024 + (r&7)*128 + (c&63)*2 ; ^(r&7)<<4
// cgrp-major => K-half kh of sc is the contiguous 32KB at (2*sc+kh)*HHALF.
__global__ void convert_weights_kernel(const float* __restrict__ cw1,
                                       const float* __restrict__ cw2,
                                       const float* __restrict__ rw1,
                                       const float* __restrict__ rw2,
                                       const float* __restrict__ rw3) {
    int i = blockIdx.x * 512 + threadIdx.x;   // 0..294911
    int sc = i >> 15;
    int e  = i & 32767;
    int r  = e >> 8, c = e & 255;
    float v = 0.f;
    if (sc < 2)       v = rw1[(sc * 128 + r) * 256 + c];
    else if (sc < 4)  v = rw2[((sc - 2) * 128 + r) * 256 + c];
    else if (sc < 5)  { if (r < 68) v = rw3[r * 256 + c]; }
    else if (sc < 7)  v = cw1[((sc - 5) * 128 + r) * 256 + c];
    else              v = cw2[((sc - 7) * 128 + r) * 256 + c];
    int byte = ((r >> 3) + (c >> 6) * 16) * 1024 + (r & 7) * 128 + (c & 63) * 2;
    byte ^= (r & 7) << 4;
    g_wh[sc * 32768 + (byte >> 1)] = __float2half(v);
}

// ------------------------------ PTX helpers --------------------------------
DINL unsigned smem_u32(const void* p) {
    unsigned a;
    asm("{ .reg .u64 t; cvta.to.shared.u64 t, %1; cvt.u32.u64 %0, t; }"
        : "=r"(a) : "l"(p));
    return a;
}
DINL void ldm4(unsigned r[4], unsigned addr) {
    asm volatile("ldmatrix.sync.aligned.m8n8.x4.shared.b16 {%0,%1,%2,%3}, [%4];"
                 : "=r"(r[0]), "=r"(r[1]), "=r"(r[2]), "=r"(r[3]) : "r"(addr));
}
DINL void mma4(float d[4], const unsigned a[4], unsigned b0, unsigned b1) {
    asm volatile(
        "mma.sync.aligned.m16n8k16.row.col.f32.f16.f16.f32 "
        "{%0,%1,%2,%3}, {%4,%5,%6,%7}, {%8,%9}, {%0,%1,%2,%3};\n"
        : "+f"(d[0]), "+f"(d[1]), "+f"(d[2]), "+f"(d[3])
        : "r"(a[0]), "r"(a[1]), "r"(a[2]), "r"(a[3]), "r"(b0), "r"(b1));
}
#define CP_COMMIT() asm volatile("cp.async.commit_group;" ::: "memory")
template <int N> DINL void cp_wait() {
    asm volatile("cp.async.wait_group %0;" :: "n"(N) : "memory");
}

// ----------------------------- staging -------------------------------------
// 32KB half-chunk: 512 threads x 4 x 16B
DINL void stageW_half(int h, unsigned sbm, int tid) {
    const __half* g = g_wh + (size_t)h * cfg::HHALF + tid * 8;
    unsigned dst = sbm + cfg::SB + (unsigned)((h & 1) * 32768) + tid * 16;
    #pragma unroll
    for (int k = 0; k < 4; ++k)
        asm volatile("cp.async.cg.shared.global [%0], [%1], 16;"
                     :: "r"(dst + k * 8192), "l"(g + k * 4096) : "memory");
}

// 128 rows x 256 f32 -> f16 into tile, blocked SW128 (512 threads)
DINL void stage_x(const float* __restrict__ x, char* smem, int tid) {
    #pragma unroll
    for (int i = tid; i < 4096; i += 512) {
        int r = i >> 5, u = i & 31;
        const float4* src = (const float4*)(x + (size_t)r * 256 + u * 8);
        float4 v0 = src[0], v1 = src[1];
        __half2 h0 = __floats2half2_rn(v0.x, v0.y);
        __half2 h1 = __floats2half2_rn(v0.z, v0.w);
        __half2 h2 = __floats2half2_rn(v1.x, v1.y);
        __half2 h3 = __floats2half2_rn(v1.z, v1.w);
        int byte = ((r >> 3) + (u >> 3) * 16) * 1024 + (r & 7) * 128 + (u & 7) * 16;
        byte ^= (r & 7) << 4;
        uint4 pk;
        pk.x = *(unsigned*)&h0; pk.y = *(unsigned*)&h1;
        pk.z = *(unsigned*)&h2; pk.w = *(unsigned*)&h3;
        *(uint4*)(smem + cfg::SA + byte) = pk;
    }
}

// prefetch next half + wait current; after this, buffer (h&1) is ready
DINL void half_wait(int h, unsigned sbm, int tid) {
    if (h + 1 < cfg::NH) {
        stageW_half(h + 1, sbm, tid);
        CP_COMMIT();
        cp_wait<1>();
    } else {
        cp_wait<0>();
    }
    __syncthreads();
}

// ---------------- 128x128 x K-half(128) GEMM via ldmatrix ------------------
// 16 warps: wm 0..3 (32 rows), wn 0..3 (32 cols). KH selects A K-half;
// B buffer holds its K-half as local cgrp 0,1. acc carries across halves.
template <int KH>
DINL void mma_half(unsigned aBase, unsigned bBase, float acc[2][4][4],
                   int lane, int wm, int wn) {
    if (KH == 0) {
        #pragma unroll
        for (int i = 0; i < 2; ++i)
            #pragma unroll
            for (int j = 0; j < 4; ++j)
                #pragma unroll
                for (int k = 0; k < 4; ++k) acc[i][j][k] = 0.f;
    }
    const int la7 = lane & 7, lb3 = (lane >> 3) & 1, lb4 = (lane >> 4) & 1;
    unsigned rowA[2], rowB[2];
    #pragma unroll
    for (int mi = 0; mi < 2; ++mi) {
        int R = wm * 32 + mi * 16 + lb3 * 8 + la7;
        rowA[mi] = aBase + (unsigned)((R >> 3) * 1024 + la7 * 128);
    }
    #pragma unroll
    for (int np = 0; np < 2; ++np) {
        int R = wn * 32 + np * 16 + lb4 * 8 + la7;
        rowB[np] = bBase + (unsigned)((R >> 3) * 1024 + la7 * 128);
    }
    #pragma unroll
    for (int k0 = 0; k0 < 8; ++k0) {
        int qa = 2 * (KH * 8 + k0) + lb4;      // global K for A
        int qb = 2 * k0 + lb3;                 // local K within buffer
        unsigned ca = (unsigned)(((qa >> 3) << 14) + (((qa & 7) ^ la7) << 4));
        unsigned cb = (unsigned)(((qb >> 3) << 14) + (((qb & 7) ^ la7) << 4));
        unsigned a0[4], a1[4], b0[4], b1[4];
        ldm4(a0, rowA[0] + ca);
        ldm4(a1, rowA[1] + ca);
        ldm4(b0, rowB[0] + cb);
        ldm4(b1, rowB[1] + cb);
        mma4(acc[0][0], a0, b0[0], b0[1]);
        mma4(acc[0][1], a0, b0[2], b0[3]);
        mma4(acc[1][0], a1, b0[0], b0[1]);
        mma4(acc[1][1], a1, b0[2], b0[3]);
        mma4(acc[0][2], a0, b1[0], b1[1]);
        mma4(acc[0][3], a0, b1[2], b1[3]);
        mma4(acc[1][2], a1, b1[0], b1[1]);
        mma4(acc[1][3], a1, b1[2], b1[3]);
    }
}

// bias + relu -> f16 into blocked SW128 tile (cbase = 0 or 128)
DINL void epi_hidden(const float acc[2][4][4], char* sOut, const float* bias,
                     int cbase, int lane, int wm, int wn) {
    #pragma unroll
    for (int mi = 0; mi < 2; ++mi) {
        int R = wm * 32 + mi * 16 + (lane >> 2);
        #pragma unroll
        for (int nj = 0; nj < 4; ++nj) {
            int C = cbase + wn * 32 + nj * 8 + (lane & 3) * 2;
            float b0 = bias[C], b1 = bias[C + 1];
            __half2 lo = __floats2half2_rn(fmaxf(acc[mi][nj][0] + b0, 0.f),
                                           fmaxf(acc[mi][nj][1] + b1, 0.f));
            __half2 hi = __floats2half2_rn(fmaxf(acc[mi][nj][2] + b0, 0.f),
                                           fmaxf(acc[mi][nj][3] + b1, 0.f));
            int byte = ((R >> 3) + (C >> 6) * 16) * 1024 + (R & 7) * 128 + (C & 63) * 2;
            byte ^= (R & 7) << 4;
            *(__half2*)(sOut + byte) = lo;
            *(__half2*)(sOut + byte + 1024) = hi;   // row R+8: next atom
        }
    }
}

// reg-pred epilogue: fp32 (cols < 68) to sReg (stride 68) + global
DINL void epi_reg(const float acc[2][4][4], float* sReg, const float* bias,
                  float* __restrict__ gReg, int row0, int lane, int wm, int wn) {
    #pragma unroll
    for (int mi = 0; mi < 2; ++mi) {
        int R = wm * 32 + mi * 16 + (lane >> 2);
        #pragma unroll
        for (int nj = 0; nj < 4; ++nj) {
            int C = wn * 32 + nj * 8 + (lane & 3) * 2;
            if (C < 68) {
                float b0 = bias[C], b1 = bias[C + 1];
                float2 lo = make_float2(acc[mi][nj][0] + b0, acc[mi][nj][1] + b1);
                float2 hi = make_float2(acc[mi][nj][2] + b0, acc[mi][nj][3] + b1);
                *(float2*)(sReg + R * 68 + C) = lo;
                *(float2*)(sReg + (R + 8) * 68 + C) = hi;
                *(float2*)(gReg + (size_t)(row0 + R) * 68 + C) = lo;
                *(float2*)(gReg + (size_t)(row0 + R + 8) * 68 + C) = hi;
            }
        }
    }
}

// one superchunk = two K-halves (h = 2*sc, 2*sc+1), acc accumulated across
#define SUPERCHUNK(scIdx, AOFF)                                              \
    do {                                                                     \
        half_wait(2 * (scIdx), sbm, tid);                                    \
        mma_half<0>(sbm + (AOFF), sbm + SB + ((2 * (scIdx)) & 1) * 32768,    \
                    acc, lane, wm, wn);                                      \
        __syncthreads();                                                     \
        half_wait(2 * (scIdx) + 1, sbm, tid);                                \
        mma_half<1>(sbm + (AOFF), sbm + SB + ((2 * (scIdx) + 1) & 1) * 32768,\
                    acc, lane, wm, wn);                                      \
    } while (0)

// ------------------------------ main kernel --------------------------------
__global__ __launch_bounds__(512, 1)
void gfocal_head_kernel(const float* __restrict__ x,
                        const float* __restrict__ cb1, const float* __restrict__ cb2,
                        const float* __restrict__ cw3, const float* __restrict__ cb3,
                        const float* __restrict__ rb1, const float* __restrict__ rb2,
                        const float* __restrict__ rb3,
                        const float* __restrict__ qw1, const float* __restrict__ qb1,
                        const float* __restrict__ qw2, const float* __restrict__ qb2,
                        float* __restrict__ out) {
    using namespace cfg;
    extern __shared__ char smem[];
    const unsigned sbm = smem_u32(smem);
    const int tid = threadIdx.x, w = tid >> 5, lane = tid & 31;
    const int wm = w >> 2, wn = w & 3;
    const int row0 = blockIdx.x * TM;

    float* out_cls = out;
    float* out_box = out + (size_t)P;
    float* out_reg = out + (size_t)P * 5;

    const float* bias = (const float*)(smem + SBIAS);

    // ---- prolog: prefetch weight half 0, small weights, stage X ----
    stageW_half(0, sbm, tid);
    CP_COMMIT();
    if (tid < 256) {
        float* fb = (float*)(smem + SBIAS);
        fb[tid] = rb1[tid]; fb[256 + tid] = rb2[tid];
        fb[512 + tid] = cb1[tid]; fb[768 + tid] = cb2[tid];
        if (tid < 68) fb[1024 + tid] = rb3[tid];
        ((float*)(smem + SCW3))[tid] = cw3[tid];
        if (tid < 64) { ((float*)(smem + SQB1))[tid] = qb1[tid];
                        ((float*)(smem + SQW2))[tid] = qw2[tid]; }
        if (tid == 0) { ((float*)(smem + SSC))[0] = qb2[0];
                        ((float*)(smem + SSC))[1] = cb3[0]; }
    }
    {
        float* q1 = (float*)(smem + SQW1);
        for (int i = tid; i < 1280; i += 512) q1[i] = qw1[i];
    }
    stage_x(x + (size_t)row0 * 256, smem, tid);

    float acc[2][4][4];

    // ---------------- regression branch ----------------
    SUPERCHUNK(0, SA);                                  // X @ rw1^T [0:128)
    epi_hidden(acc, smem + SH, bias, 0, lane, wm, wn);
    __syncthreads();
    SUPERCHUNK(1, SA);                                  // X @ rw1^T [128:256)
    epi_hidden(acc, smem + SH, bias, 128, lane, wm, wn);
    __syncthreads();
    SUPERCHUNK(2, SH);                                  // h1 @ rw2^T [0:128)
    epi_hidden(acc, smem + SA, bias + 256, 0, lane, wm, wn);
    __syncthreads();
    SUPERCHUNK(3, SH);                                  // h1 @ rw2^T [128:256)
    epi_hidden(acc, smem + SA, bias + 256, 128, lane, wm, wn);
    __syncthreads();
    SUPERCHUNK(4, SA);                                  // reg_pred (68 cols)
    epi_reg(acc, (float*)(smem + SH), bias + 1024, out_reg, row0, lane, wm, wn);
    __syncthreads();
    // NOTE: cls half 10 already prefetched during superchunk 4's second half.

    // ---- stats: softmax, box, top-4 -> sStat (thread = (row, direction)) ----
    {
        int row = tid >> 2, d = tid & 3;
        const float* rp = (const float*)(smem + SH) + row * 68 + d * 17;
        float* sStat = (float*)(smem + SSTAT);
        float pb[17];
        float mx = -1e30f;
        #pragma unroll
        for (int b = 0; b < 17; ++b) { pb[b] = rp[b]; mx = fmaxf(mx, pb[b]); }
        float s = 0.f, sbi = 0.f;
        #pragma unroll
        for (int b = 0; b < 17; ++b) {
            float e = __expf(pb[b] - mx);
            pb[b] = e; s += e; sbi += e * (float)b;
        }
        float inv = 1.f / s;
        out_box[(size_t)(row0 + row) * 4 + d] = sbi * inv * (1.f / 16.f);
        unsigned mask = 0; float tsum = 0.f;
        #pragma unroll
        for (int j = 0; j < 4; ++j) {
            float m = -1e30f; int mi = 0;
            #pragma unroll
            for (int b = 0; b < 17; ++b) {
                bool ok = !((mask >> b) & 1u) && (pb[b] > m);
                if (ok) { m = pb[b]; mi = b; }
            }
            mask |= (1u << mi);
            tsum += m;
            sStat[row * 21 + d * 5 + j] = m * inv;
        }
        sStat[row * 21 + d * 5 + 4] = tsum * inv * 0.25f;
    }
    __syncthreads();

    // ---- quality (tid<128) + restage X for cls (all threads) ----
    if (tid < TM) {
        const float* st = (const float*)(smem + SSTAT) + tid * 21;
        const float* q1 = (const float*)(smem + SQW1);
        const float* qb = (const float*)(smem + SQB1);
        const float* q2 = (const float*)(smem + SQW2);
        float q = ((const float*)(smem + SSC))[0];
        #pragma unroll 4
        for (int o = 0; o < 64; ++o) {
            float h = qb[o];
            #pragma unroll
            for (int c = 0; c < 20; ++c) h += q1[o * 20 + c] * st[c];
            q += q2[o] * fmaxf(h, 0.f);
        }
        ((float*)(smem + SQUAL))[tid] = 1.f / (1.f + __expf(-q));
    }
    stage_x(x + (size_t)row0 * 256, smem, tid);

    // ---------------- classification branch ----------------
    SUPERCHUNK(5, SA);                                  // X @ cw1^T [0:128)
    epi_hidden(acc, smem + SH, bias + 512, 0, lane, wm, wn);
    __syncthreads();
    SUPERCHUNK(6, SA);                                  // X @ cw1^T [128:256)
    epi_hidden(acc, smem + SH, bias + 512, 128, lane, wm, wn);
    __syncthreads();
    SUPERCHUNK(7, SH);                                  // h1 @ cw2^T [0:128)
    epi_hidden(acc, smem + SA, bias + 768, 0, lane, wm, wn);
    __syncthreads();
    SUPERCHUNK(8, SH);                                  // h1 @ cw2^T [128:256)
    epi_hidden(acc, smem + SA, bias + 768, 128, lane, wm, wn);
    __syncthreads();

    // ---- cls L3: dot(h2c, cw3) + cb3, sigmoid, * quality ----
    if (tid < TM) {
        int r = tid, r7 = r & 7;
        unsigned rbase = (unsigned)((r >> 3) * 1024 + r7 * 128);
        const float* w3 = (const float*)(smem + SCW3);
        float a = ((const float*)(smem + SSC))[1];
        #pragma unroll
        for (int cg = 0; cg < 4; ++cg) {
            #pragma unroll
            for (int u = 0; u < 8; ++u) {
                const __half2* p = (const __half2*)(smem + SA + rbase +
                                                    cg * 16384 + ((u ^ r7) << 4));
                const float* wseg = w3 + cg * 64 + u * 8;
                #pragma unroll
                for (int j = 0; j < 4; ++j) {
                    float2 v = __half22float2(p[j]);
                    a += v.x * wseg[2 * j] + v.y * wseg[2 * j + 1];
                }
            }
        }
        float csig = 1.f / (1.f + __expf(-a));
        out_cls[row0 + r] = csig * ((const float*)(smem + SQUAL))[r];
    }
}

// ------------------------------ launcher -----------------------------------
extern "C" void kernel_launch(void* const* d_in, const int* in_sizes, int n_in,
                              void* d_out, int out_size) {
    const float* x   = (const float*)d_in[0];
    const float* cw1 = (const float*)d_in[1];
    const float* cb1 = (const float*)d_in[2];
    const float* cw2 = (const float*)d_in[3];
    const float* cb2 = (const float*)d_in[4];
    const float* cw3 = (const float*)d_in[5];
    const float* cb3 = (const float*)d_in[6];
    const float* rw1 = (const float*)d_in[7];
    const float* rb1 = (const float*)d_in[8];
    const float* rw2 = (const float*)d_in[9];
    const float* rb2 = (const float*)d_in[10];
    const float* rw3 = (const float*)d_in[11];
    const float* rb3 = (const float*)d_in[12];
    const float* qw1 = (const float*)d_in[13];
    const float* qb1 = (const float*)d_in[14];
    const float* qw2 = (const float*)d_in[15];
    const float* qb2 = (const float*)d_in[16];
    float* out = (float*)d_out;

    cudaFuncSetAttribute(gfocal_head_kernel,
                         cudaFuncAttributeMaxDynamicSharedMemorySize, cfg::SMEMB);

    convert_weights_kernel<<<cfg::NH * cfg::HHALF / 512, 512>>>(cw1, cw2, rw1, rw2, rw3);
    gfocal_head_kernel<<<cfg::NBLK, 512, cfg::SMEMB>>>(
        x, cb1, cb2, cw3, cb3, rb1, rb2, rb3, qw1, qb1, qw2, qb2, out);
}

// round 12
// speedup vs baseline: 1.3035x; 1.0013x over previous
#include <cuda_runtime.h>
#include <cuda_fp16.h>

#define DINL __device__ __forceinline__

// ---------------------------------------------------------------------------
// GFocalV2 head (sm_103): fused 3-layer MLPs via mma.sync.m16n8k16 + ldmatrix.
// 512 threads / 16 warps, warp tile 64x32 covering the FULL 128x256 layer in
// one sweep; layer weights (128KB) fully resident; layer output register-
// resident then written in place over the activation tile (no ping-pong).
// ---------------------------------------------------------------------------

namespace cfg {
constexpr int P    = 32 * 96 * 96;   // 294912
constexpr int TM   = 128;            // rows per CTA
constexpr int NBLK = P / TM;         // 2304
constexpr int HHALF = 16384;         // halves per 32KB piece
constexpr int NH   = 18;             // pieces in weight cache

// dynamic smem (bytes)
constexpr int SA    = 0;             // 128x256 f16 blocked SW128 (64 KB), in-place I/O
constexpr int SB    = 65536;         // 4 x 32KB weight pieces (full layer)
constexpr int SBIAS = 196608;        // rb1 +0, rb2 +1024, cb1 +2048, cb2 +3072, rb3 +4096
constexpr int SSTAT = SBIAS + 4608;  // 128*21 f32
constexpr int SQW1  = SSTAT + 10752;
constexpr int SQB1  = SQW1 + 5120;
constexpr int SQW2  = SQB1 + 256;
constexpr int SQW2E = SQW2 + 256;
constexpr int SCW3  = SQW2E;
constexpr int SQUAL = SCW3 + 1024;
constexpr int SSC   = SQUAL + 512;
constexpr int SMEMB = SSC + 16;      // ~219 KB
}  // namespace cfg

__device__ __align__(16) __half g_wh[cfg::NH * cfg::HHALF];

// --------------------- weight fp32 -> fp16 pre-swizzled --------------------
// superchunk sc = 128 out-rows x 256 cols; atom = 8 rows x 64 halves;
// atom = (r>>3) + (c>>6)*16 ; byte = atom*1024 + (r&7)*128 + (c&63)*2 ; ^(r&7)<<4
// cgrp-major: K-half kh of sc contiguous 32KB at (2*sc+kh)*HHALF.
// Layers: L0=rw1 pieces 0..3, L1=rw2 4..7, L2=rw3 8..9, L3=cw1 10..13, L4=cw2 14..17
__global__ void convert_weights_kernel(const float* __restrict__ cw1,
                                       const float* __restrict__ cw2,
                                       const float* __restrict__ rw1,
                                       const float* __restrict__ rw2,
                                       const float* __restrict__ rw3) {
    int i = blockIdx.x * 512 + threadIdx.x;   // 0..294911
    int sc = i >> 15;
    int e  = i & 32767;
    int r  = e >> 8, c = e & 255;
    float v = 0.f;
    if (sc < 2)       v = rw1[(sc * 128 + r) * 256 + c];
    else if (sc < 4)  v = rw2[((sc - 2) * 128 + r) * 256 + c];
    else if (sc < 5)  { if (r < 68) v = rw3[r * 256 + c]; }
    else if (sc < 7)  v = cw1[((sc - 5) * 128 + r) * 256 + c];
    else              v = cw2[((sc - 7) * 128 + r) * 256 + c];
    int byte = ((r >> 3) + (c >> 6) * 16) * 1024 + (r & 7) * 128 + (c & 63) * 2;
    byte ^= (r & 7) << 4;
    g_wh[sc * 32768 + (byte >> 1)] = __float2half(v);
}

// ------------------------------ PTX helpers --------------------------------
DINL unsigned smem_u32(const void* p) {
    unsigned a;
    asm("{ .reg .u64 t; cvta.to.shared.u64 t, %1; cvt.u32.u64 %0, t; }"
        : "=r"(a) : "l"(p));
    return a;
}
DINL void ldm4(unsigned r[4], unsigned addr) {
    asm volatile("ldmatrix.sync.aligned.m8n8.x4.shared.b16 {%0,%1,%2,%3}, [%4];"
                 : "=r"(r[0]), "=r"(r[1]), "=r"(r[2]), "=r"(r[3]) : "r"(addr));
}
DINL void mma4(float d[4], const unsigned a[4], unsigned b0, unsigned b1) {
    asm volatile(
        "mma.sync.aligned.m16n8k16.row.col.f32.f16.f16.f32 "
        "{%0,%1,%2,%3}, {%4,%5,%6,%7}, {%8,%9}, {%0,%1,%2,%3};\n"
        : "+f"(d[0]), "+f"(d[1]), "+f"(d[2]), "+f"(d[3])
        : "r"(a[0]), "r"(a[1]), "r"(a[2]), "r"(a[3]), "r"(b0), "r"(b1));
}
#define CP_COMMIT() asm volatile("cp.async.commit_group;" ::: "memory")
template <int N> DINL void cp_wait() {
    asm volatile("cp.async.wait_group %0;" :: "n"(N) : "memory");
}

// ----------------------------- staging -------------------------------------
// stage npieces x 32KB of layer weights (contiguous in g_wh) into SB
DINL void stage_layer(int h0, int npieces, unsigned sbm, int tid) {
    const __half* g = g_wh + (size_t)h0 * cfg::HHALF + tid * 8;
    unsigned dst = sbm + cfg::SB + tid * 16;
    for (int j = 0; j < npieces * 4; ++j)
        asm volatile("cp.async.cg.shared.global [%0], [%1], 16;"
                     :: "r"(dst + j * 8192), "l"(g + j * 4096) : "memory");
    CP_COMMIT();
}

// 128 rows x 256 f32 -> f16 into SA, blocked SW128 (512 threads)
DINL void stage_x(const float* __restrict__ x, char* smem, int tid) {
    #pragma unroll
    for (int i = tid; i < 4096; i += 512) {
        int r = i >> 5, u = i & 31;
        const float4* src = (const float4*)(x + (size_t)r * 256 + u * 8);
        float4 v0 = src[0], v1 = src[1];
        __half2 h0 = __floats2half2_rn(v0.x, v0.y);
        __half2 h1 = __floats2half2_rn(v0.z, v0.w);
        __half2 h2 = __floats2half2_rn(v1.x, v1.y);
        __half2 h3 = __floats2half2_rn(v1.z, v1.w);
        int byte = ((r >> 3) + (u >> 3) * 16) * 1024 + (r & 7) * 128 + (u & 7) * 16;
        byte ^= (r & 7) << 4;
        uint4 pk;
        pk.x = *(unsigned*)&h0; pk.y = *(unsigned*)&h1;
        pk.z = *(unsigned*)&h2; pk.w = *(unsigned*)&h3;
        *(uint4*)(smem + cfg::SA + byte) = pk;
    }
}

// ---------------- full-layer 128x256 GEMM, warp tile 64x32 -----------------
// 16 warps: wm 0..1 (64 rows), wn 0..7 (32 cols). A: full K=256 in SA.
// B piece p (32KB) = 128 out-rows x K-half; warp's n-range selects piece pair.
template <int NP>   // 4 = full 256-col layer, 2 = 128-col (reg) layer
DINL void mma_layer(unsigned aBase, unsigned bBase, float acc[4][4][4],
                    int lane, int wm, int wn) {
    #pragma unroll
    for (int i = 0; i < 4; ++i)
        #pragma unroll
        for (int j = 0; j < 4; ++j)
            #pragma unroll
            for (int k = 0; k < 4; ++k) acc[i][j][k] = 0.f;
    if (NP == 2 && wn >= 4) return;

    const int la7 = lane & 7, lb3 = (lane >> 3) & 1, lb4 = (lane >> 4) & 1;
    unsigned rowA[4], rowB[2];
    #pragma unroll
    for (int mi = 0; mi < 4; ++mi) {
        int R = wm * 64 + mi * 16 + lb3 * 8 + la7;
        rowA[mi] = aBase + (unsigned)((R >> 3) * 1024 + la7 * 128);
    }
    const unsigned bsel = (wn >= 4) ? 65536u : 0u;    // piece pair for n>=128
    #pragma unroll
    for (int np = 0; np < 2; ++np) {
        int R = (wn & 3) * 32 + np * 16 + lb4 * 8 + la7;
        rowB[np] = bBase + bsel + (unsigned)((R >> 3) * 1024 + la7 * 128);
    }
    #pragma unroll
    for (int k0 = 0; k0 < 16; ++k0) {
        int qa  = 2 * k0 + lb4;            // A word in full-K row
        int qbl = 2 * (k0 & 7) + lb3;      // B word within K-half piece
        unsigned ca = (unsigned)(((qa >> 3) << 14) + (((qa & 7) ^ la7) << 4));
        unsigned cb = (unsigned)((k0 >= 8 ? 32768 : 0) +
                                 ((qbl >> 3) << 14) + (((qbl & 7) ^ la7) << 4));
        unsigned a0[4], a1[4], a2[4], a3[4], b0[4], b1[4];
        ldm4(a0, rowA[0] + ca);
        ldm4(a1, rowA[1] + ca);
        ldm4(a2, rowA[2] + ca);
        ldm4(a3, rowA[3] + ca);
        ldm4(b0, rowB[0] + cb);
        ldm4(b1, rowB[1] + cb);
        mma4(acc[0][0], a0, b0[0], b0[1]); mma4(acc[0][1], a0, b0[2], b0[3]);
        mma4(acc[0][2], a0, b1[0], b1[1]); mma4(acc[0][3], a0, b1[2], b1[3]);
        mma4(acc[1][0], a1, b0[0], b0[1]); mma4(acc[1][1], a1, b0[2], b0[3]);
        mma4(acc[1][2], a1, b1[0], b1[1]); mma4(acc[1][3], a1, b1[2], b1[3]);
        mma4(acc[2][0], a2, b0[0], b0[1]); mma4(acc[2][1], a2, b0[2], b0[3]);
        mma4(acc[2][2], a2, b1[0], b1[1]); mma4(acc[2][3], a2, b1[2], b1[3]);
        mma4(acc[3][0], a3, b0[0], b0[1]); mma4(acc[3][1], a3, b0[2], b0[3]);
        mma4(acc[3][2], a3, b1[0], b1[1]); mma4(acc[3][3], a3, b1[2], b1[3]);
    }
}

// bias + relu -> f16 IN PLACE into SA (blocked SW128), full 256 cols
DINL void epi_hidden(const float acc[4][4][4], char* sOut, const float* bias,
                     int lane, int wm, int wn) {
    #pragma unroll
    for (int mi = 0; mi < 4; ++mi) {
        int R = wm * 64 + mi * 16 + (lane >> 2);
        #pragma unroll
        for (int nj = 0; nj < 4; ++nj) {
            int C = wn * 32 + nj * 8 + (lane & 3) * 2;
            float b0 = bias[C], b1 = bias[C + 1];
            __half2 lo = __floats2half2_rn(fmaxf(acc[mi][nj][0] + b0, 0.f),
                                           fmaxf(acc[mi][nj][1] + b1, 0.f));
            __half2 hi = __floats2half2_rn(fmaxf(acc[mi][nj][2] + b0, 0.f),
                                           fmaxf(acc[mi][nj][3] + b1, 0.f));
            int byte = ((R >> 3) + (C >> 6) * 16) * 1024 + (R & 7) * 128 + (C & 63) * 2;
            byte ^= (R & 7) << 4;
            *(__half2*)(sOut + byte) = lo;
            *(__half2*)(sOut + byte + 1024) = hi;   // row R+8: next atom
        }
    }
}

// reg-pred epilogue: fp32 (cols < 68) IN PLACE into SA (stride 68) + global
DINL void epi_reg(const float acc[4][4][4], float* sReg, const float* bias,
                  float* __restrict__ gReg, int row0, int lane, int wm, int wn) {
    if (wn >= 3) return;
    #pragma unroll
    for (int mi = 0; mi < 4; ++mi) {
        int R = wm * 64 + mi * 16 + (lane >> 2);
        #pragma unroll
        for (int nj = 0; nj < 4; ++nj) {
            int C = wn * 32 + nj * 8 + (lane & 3) * 2;
            if (C < 68) {
                float b0 = bias[C], b1 = bias[C + 1];
                float2 lo = make_float2(acc[mi][nj][0] + b0, acc[mi][nj][1] + b1);
                float2 hi = make_float2(acc[mi][nj][2] + b0, acc[mi][nj][3] + b1);
                *(float2*)(sReg + R * 68 + C) = lo;
                *(float2*)(sReg + (R + 8) * 68 + C) = hi;
                *(float2*)(gReg + (size_t)(row0 + R) * 68 + C) = lo;
                *(float2*)(gReg + (size_t)(row0 + R + 8) * 68 + C) = hi;
            }
        }
    }
}

// ------------------------------ main kernel --------------------------------
__global__ __launch_bounds__(512, 1)
void gfocal_head_kernel(const float* __restrict__ x,
                        const float* __restrict__ cb1, const float* __restrict__ cb2,
                        const float* __restrict__ cw3, const float* __restrict__ cb3,
                        const float* __restrict__ rb1, const float* __restrict__ rb2,
                        const float* __restrict__ rb3,
                        const float* __restrict__ qw1, const float* __restrict__ qb1,
                        const float* __restrict__ qw2, const float* __restrict__ qb2,
                        float* __restrict__ out) {
    using namespace cfg;
    extern __shared__ char smem[];
    const unsigned sbm = smem_u32(smem);
    const int tid = threadIdx.x, w = tid >> 5, lane = tid & 31;
    const int wm = w >> 3, wn = w & 7;        // 2 x 8 warp grid, tile 64x32
    const int row0 = blockIdx.x * TM;

    float* out_cls = out;
    float* out_box = out + (size_t)P;
    float* out_reg = out + (size_t)P * 5;

    const float* bias = (const float*)(smem + SBIAS);

    // ---- prolog: prefetch L0 weights, small weights, stage X ----
    stage_layer(0, 4, sbm, tid);
    if (tid < 256) {
        float* fb = (float*)(smem + SBIAS);
        fb[tid] = rb1[tid]; fb[256 + tid] = rb2[tid];
        fb[512 + tid] = cb1[tid]; fb[768 + tid] = cb2[tid];
        if (tid < 68) fb[1024 + tid] = rb3[tid];
        ((float*)(smem + SCW3))[tid] = cw3[tid];
        if (tid < 64) { ((float*)(smem + SQB1))[tid] = qb1[tid];
                        ((float*)(smem + SQW2))[tid] = qw2[tid]; }
        if (tid == 0) { ((float*)(smem + SSC))[0] = qb2[0];
                        ((float*)(smem + SSC))[1] = cb3[0]; }
    }
    {
        float* q1 = (float*)(smem + SQW1);
        for (int i = tid; i < 1280; i += 512) q1[i] = qw1[i];
    }
    stage_x(x + (size_t)row0 * 256, smem, tid);

    float acc[4][4][4];

    // ---------------- regression branch ----------------
    cp_wait<0>(); __syncthreads();
    mma_layer<4>(sbm + SA, sbm + SB, acc, lane, wm, wn);   // X @ rw1^T
    __syncthreads();
    stage_layer(4, 4, sbm, tid);                           // prefetch rw2
    epi_hidden(acc, smem + SA, bias, lane, wm, wn);        // SA = h1r

    cp_wait<0>(); __syncthreads();
    mma_layer<4>(sbm + SA, sbm + SB, acc, lane, wm, wn);   // h1 @ rw2^T
    __syncthreads();
    stage_layer(8, 2, sbm, tid);                           // prefetch rw3
    epi_hidden(acc, smem + SA, bias + 256, lane, wm, wn);  // SA = h2r

    cp_wait<0>(); __syncthreads();
    mma_layer<2>(sbm + SA, sbm + SB, acc, lane, wm, wn);   // h2 @ rw3^T
    __syncthreads();
    stage_layer(10, 4, sbm, tid);                          // prefetch cw1
    epi_reg(acc, (float*)(smem + SA), bias + 1024, out_reg, row0, lane, wm, wn);
    __syncthreads();

    // ---- stats: softmax, box, top-4 -> sStat (thread = (row, direction)) ----
    {
        int row = tid >> 2, d = tid & 3;
        const float* rp = (const float*)(smem + SA) + row * 68 + d * 17;
        float* sStat = (float*)(smem + SSTAT);
        float pb[17];
        float mx = -1e30f;
        #pragma unroll
        for (int b = 0; b < 17; ++b) { pb[b] = rp[b]; mx = fmaxf(mx, pb[b]); }
        float s = 0.f, sbi = 0.f;
        #pragma unroll
        for (int b = 0; b < 17; ++b) {
            float e = __expf(pb[b] - mx);
            pb[b] = e; s += e; sbi += e * (float)b;
        }
        float inv = 1.f / s;
        out_box[(size_t)(row0 + row) * 4 + d] = sbi * inv * (1.f / 16.f);
        unsigned mask = 0; float tsum = 0.f;
        #pragma unroll
        for (int j = 0; j < 4; ++j) {
            float m = -1e30f; int mi = 0;
            #pragma unroll
            for (int b = 0; b < 17; ++b) {
                bool ok = !((mask >> b) & 1u) && (pb[b] > m);
                if (ok) { m = pb[b]; mi = b; }
            }
            mask |= (1u << mi);
            tsum += m;
            sStat[row * 21 + d * 5 + j] = m * inv;
        }
        sStat[row * 21 + d * 5 + 4] = tsum * inv * 0.25f;
    }
    __syncthreads();

    // ---- quality (tid<128) + restage X for cls (all threads) ----
    if (tid < TM) {
        const float* st = (const float*)(smem + SSTAT) + tid * 21;
        const float* q1 = (const float*)(smem + SQW1);
        const float* qb = (const float*)(smem + SQB1);
        const float* q2 = (const float*)(smem + SQW2);
        float q = ((const float*)(smem + SSC))[0];
        #pragma unroll 4
        for (int o = 0; o < 64; ++o) {
            float h = qb[o];
            #pragma unroll
            for (int c = 0; c < 20; ++c) h += q1[o * 20 + c] * st[c];
            q += q2[o] * fmaxf(h, 0.f);
        }
        ((float*)(smem + SQUAL))[tid] = 1.f / (1.f + __expf(-q));
    }
    stage_x(x + (size_t)row0 * 256, smem, tid);            // SA = X again

    // ---------------- classification branch ----------------
    cp_wait<0>(); __syncthreads();
    mma_layer<4>(sbm + SA, sbm + SB, acc, lane, wm, wn);   // X @ cw1^T
    __syncthreads();
    stage_layer(14, 4, sbm, tid);                          // prefetch cw2
    epi_hidden(acc, smem + SA, bias + 512, lane, wm, wn);  // SA = h1c

    cp_wait<0>(); __syncthreads();
    mma_layer<4>(sbm + SA, sbm + SB, acc, lane, wm, wn);   // h1 @ cw2^T
    __syncthreads();
    epi_hidden(acc, smem + SA, bias + 768, lane, wm, wn);  // SA = h2c
    __syncthreads();

    // ---- cls L3: dot(h2c, cw3) + cb3, sigmoid, * quality ----
    if (tid < TM) {
        int r = tid, r7 = r & 7;
        unsigned rbase = (unsigned)((r >> 3) * 1024 + r7 * 128);
        const float* w3 = (const float*)(smem + SCW3);
        float a = ((const float*)(smem + SSC))[1];
        #pragma unroll
        for (int cg = 0; cg < 4; ++cg) {
            #pragma unroll
            for (int u = 0; u < 8; ++u) {
                const __half2* p = (const __half2*)(smem + SA + rbase +
                                                    cg * 16384 + ((u ^ r7) << 4));
                const float* wseg = w3 + cg * 64 + u * 8;
                #pragma unroll
                for (int j = 0; j < 4; ++j) {
                    float2 v = __half22float2(p[j]);
                    a += v.x * wseg[2 * j] + v.y * wseg[2 * j + 1];
                }
            }
        }
        float csig = 1.f / (1.f + __expf(-a));
        out_cls[row0 + r] = csig * ((const float*)(smem + SQUAL))[r];
    }
}

// ------------------------------ launcher -----------------------------------
extern "C" void kernel_launch(void* const* d_in, const int* in_sizes, int n_in,
                              void* d_out, int out_size) {
    const float* x   = (const float*)d_in[0];
    const float* cw1 = (const float*)d_in[1];
    const float* cb1 = (const float*)d_in[2];
    const float* cw2 = (const float*)d_in[3];
    const float* cb2 = (const float*)d_in[4];
    const float* cw3 = (const float*)d_in[5];
    const float* cb3 = (const float*)d_in[6];
    const float* rw1 = (const float*)d_in[7];
    const float* rb1 = (const float*)d_in[8];
    const float* rw2 = (const float*)d_in[9];
    const float* rb2 = (const float*)d_in[10];
    const float* rw3 = (const float*)d_in[11];
    const float* rb3 = (const float*)d_in[12];
    const float* qw1 = (const float*)d_in[13];
    const float* qb1 = (const float*)d_in[14];
    const float* qw2 = (const float*)d_in[15];
    const float* qb2 = (const float*)d_in[16];
    float* out = (float*)d_out;

    cudaFuncSetAttribute(gfocal_head_kernel,
                         cudaFuncAttributeMaxDynamicSharedMemorySize, cfg::SMEMB);

    convert_weights_kernel<<<cfg::NH * cfg::HHALF / 512, 512>>>(cw1, cw2, rw1, rw2, rw3);
    gfocal_head_kernel<<<cfg::NBLK, 512, cfg::SMEMB>>>(
        x, cb1, cb2, cw3, cb3, rb1, rb2, rb3, qw1, qb1, qw2, qb2, out);
}